// round 3
// baseline (speedup 1.0000x reference)
#include <cuda_runtime.h>
#include <math.h>

#define NN 4096
#define DD 256
#define HH 8
#define HDIM 32
#define EPS 1e-5f

// ---------------- scratch (device globals: allocation-free) ----------------
__device__ float g_q[NN * DD];
__device__ float g_k[NN * DD];
__device__ float g_v[NN * DD];
__device__ float g_o[NN * DD];   // attention output (pre-Wo)
__device__ float g_h[NN * DD];   // o @ Wo^T + bo
__device__ float g_x1[NN * DD];  // after first LN
__device__ float g_f1[NN * 2 * DD];
__device__ float g_f2[NN * DD];

// ---------------- GEMM: C[M,Nn] = A[M,K] @ B[Nn,K]^T + bias, opt relu ------
// BM=64, BN=64, BK=16, 256 threads, 4x4 microtile per thread.
__global__ void gemm_bias_kernel(const float* __restrict__ A,
                                 const float* __restrict__ B,
                                 const float* __restrict__ bias,
                                 float* __restrict__ C,
                                 int M, int Nn, int K, int relu) {
    __shared__ float As[16][64];
    __shared__ float Bs[16][64];

    const int tid = threadIdx.x;
    const int m0 = blockIdx.y * 64;
    const int n0 = blockIdx.x * 64;

    const int lrow = tid >> 2;   // 0..63
    const int lkq  = tid & 3;    // 0..3 (float4 chunk along K)

    const int tm = (tid >> 4) * 4;   // 0..60
    const int tn = (tid & 15) * 4;   // 0..60

    float acc[4][4];
#pragma unroll
    for (int i = 0; i < 4; i++)
#pragma unroll
        for (int j = 0; j < 4; j++) acc[i][j] = 0.f;

    for (int k0 = 0; k0 < K; k0 += 16) {
        float4 a4 = *reinterpret_cast<const float4*>(A + (size_t)(m0 + lrow) * K + k0 + lkq * 4);
        float4 b4 = *reinterpret_cast<const float4*>(B + (size_t)(n0 + lrow) * K + k0 + lkq * 4);
        As[lkq * 4 + 0][lrow] = a4.x;
        As[lkq * 4 + 1][lrow] = a4.y;
        As[lkq * 4 + 2][lrow] = a4.z;
        As[lkq * 4 + 3][lrow] = a4.w;
        Bs[lkq * 4 + 0][lrow] = b4.x;
        Bs[lkq * 4 + 1][lrow] = b4.y;
        Bs[lkq * 4 + 2][lrow] = b4.z;
        Bs[lkq * 4 + 3][lrow] = b4.w;
        __syncthreads();

#pragma unroll
        for (int k = 0; k < 16; k++) {
            float4 av = *reinterpret_cast<const float4*>(&As[k][tm]);
            float4 bv = *reinterpret_cast<const float4*>(&Bs[k][tn]);
            float ar[4] = {av.x, av.y, av.z, av.w};
            float br[4] = {bv.x, bv.y, bv.z, bv.w};
#pragma unroll
            for (int i = 0; i < 4; i++)
#pragma unroll
                for (int j = 0; j < 4; j++)
                    acc[i][j] = fmaf(ar[i], br[j], acc[i][j]);
        }
        __syncthreads();
    }

#pragma unroll
    for (int i = 0; i < 4; i++) {
        int row = m0 + tm + i;
#pragma unroll
        for (int j = 0; j < 4; j++) {
            int col = n0 + tn + j;
            float v = acc[i][j] + bias[col];
            if (relu) v = fmaxf(v, 0.f);
            C[(size_t)row * Nn + col] = v;
        }
    }
}

// ---------------- masked flash attention --------------------------------
// grid: (NN/128, HH), 128 threads; thread owns one query row of one head.
__global__ void attn_kernel(const float* __restrict__ q,
                            const float* __restrict__ k,
                            const float* __restrict__ v,
                            const int* __restrict__ adj,
                            float* __restrict__ o) {
    const int h = blockIdx.y;
    const int r = blockIdx.x * 128 + threadIdx.x;
    const int tid = threadIdx.x;

    __shared__ float Ks[32][HDIM];
    __shared__ float Vs[32][HDIM];

    const float scale = 0.17677669529663687f;  // 1/sqrt(32)
    float qr[HDIM];
    const float* qp = q + (size_t)r * DD + h * HDIM;
#pragma unroll
    for (int e = 0; e < HDIM; e++) qr[e] = qp[e] * scale;

    float m = -1e30f, l = 0.f;
    float acc[HDIM];
#pragma unroll
    for (int e = 0; e < HDIM; e++) acc[e] = 0.f;

    const int* arow = adj + (size_t)r * NN;

    for (int c0 = 0; c0 < NN; c0 += 32) {
        __syncthreads();
        // cooperative load of K/V tile: 32 rows x 32 floats = 256 float4 each
#pragma unroll
        for (int i = tid; i < 256; i += 128) {
            int row = i >> 3, c4 = i & 7;
            reinterpret_cast<float4*>(&Ks[row][0])[c4] =
                reinterpret_cast<const float4*>(k + (size_t)(c0 + row) * DD + h * HDIM)[c4];
            reinterpret_cast<float4*>(&Vs[row][0])[c4] =
                reinterpret_cast<const float4*>(v + (size_t)(c0 + row) * DD + h * HDIM)[c4];
        }
        __syncthreads();

        // adjacency mask bits for my row (self-loop allowed)
        unsigned mb = 0;
        const int4* a4p = reinterpret_cast<const int4*>(arow + c0);
#pragma unroll
        for (int j = 0; j < 8; j++) {
            int4 a = a4p[j];
            int base = j * 4;
            if (a.x || (c0 + base + 0) == r) mb |= 1u << (base + 0);
            if (a.y || (c0 + base + 1) == r) mb |= 1u << (base + 1);
            if (a.z || (c0 + base + 2) == r) mb |= 1u << (base + 2);
            if (a.w || (c0 + base + 3) == r) mb |= 1u << (base + 3);
        }

        float s[32];
        float tmax = -1e30f;
#pragma unroll
        for (int cc = 0; cc < 32; cc++) {
            float d = 0.f;
#pragma unroll
            for (int e = 0; e < HDIM; e++) d = fmaf(qr[e], Ks[cc][e], d);
            s[cc] = d;
            if ((mb >> cc) & 1u) tmax = fmaxf(tmax, d);
        }

        float newm = fmaxf(m, tmax);
        float corr = __expf(m - newm);
        l *= corr;
#pragma unroll
        for (int e = 0; e < HDIM; e++) acc[e] *= corr;

#pragma unroll
        for (int cc = 0; cc < 32; cc++) {
            float p = ((mb >> cc) & 1u) ? __expf(s[cc] - newm) : 0.f;
            l += p;
#pragma unroll
            for (int e = 0; e < HDIM; e++) acc[e] = fmaf(p, Vs[cc][e], acc[e]);
        }
        m = newm;
    }

    float inv = 1.0f / l;
    float* op = o + (size_t)r * DD + h * HDIM;
#pragma unroll
    for (int e = 0; e < HDIM; e++) op[e] = acc[e] * inv;
}

// ---------------- residual add + layernorm -------------------------------
// grid: NN blocks, 256 threads (one per feature)
__global__ void ln_kernel(const float* __restrict__ a,
                          const float* __restrict__ res,
                          const float* __restrict__ g,
                          const float* __restrict__ beta,
                          float* __restrict__ out) {
    const int row = blockIdx.x;
    const int t = threadIdx.x;
    const int lane = t & 31, warp = t >> 5;

    float x = a[(size_t)row * DD + t] + res[(size_t)row * DD + t];
    float s = x, s2 = x * x;
#pragma unroll
    for (int off = 16; off; off >>= 1) {
        s  += __shfl_xor_sync(0xffffffffu, s, off);
        s2 += __shfl_xor_sync(0xffffffffu, s2, off);
    }
    __shared__ float sh[2][8];
    if (lane == 0) { sh[0][warp] = s; sh[1][warp] = s2; }
    __syncthreads();
    float S = 0.f, S2 = 0.f;
#pragma unroll
    for (int i = 0; i < 8; i++) { S += sh[0][i]; S2 += sh[1][i]; }

    float mu = S * (1.0f / DD);
    float var = S2 * (1.0f / DD) - mu * mu;
    float r = rsqrtf(var + EPS);
    out[(size_t)row * DD + t] = (x - mu) * r * g[t] + beta[t];
}

// ---------------- launch --------------------------------------------------
extern "C" void kernel_launch(void* const* d_in, const int* in_sizes, int n_in,
                              void* d_out, int out_size) {
    const float* x    = (const float*)d_in[0];
    const int*   adj  = (const int*)d_in[1];
    const float* Wq   = (const float*)d_in[2];
    const float* Wk   = (const float*)d_in[3];
    const float* Wv   = (const float*)d_in[4];
    const float* bq   = (const float*)d_in[5];
    const float* bk   = (const float*)d_in[6];
    const float* bv   = (const float*)d_in[7];
    const float* Wo   = (const float*)d_in[8];
    const float* bo   = (const float*)d_in[9];
    const float* g1   = (const float*)d_in[10];
    const float* be1  = (const float*)d_in[11];
    const float* W1   = (const float*)d_in[12];
    const float* b1   = (const float*)d_in[13];
    const float* W2   = (const float*)d_in[14];
    const float* b2   = (const float*)d_in[15];
    const float* g2   = (const float*)d_in[16];
    const float* be2  = (const float*)d_in[17];
    float* out = (float*)d_out;

    float *q, *k, *v, *o, *h, *x1, *f1, *f2;
    cudaGetSymbolAddress((void**)&q,  g_q);
    cudaGetSymbolAddress((void**)&k,  g_k);
    cudaGetSymbolAddress((void**)&v,  g_v);
    cudaGetSymbolAddress((void**)&o,  g_o);
    cudaGetSymbolAddress((void**)&h,  g_h);
    cudaGetSymbolAddress((void**)&x1, g_x1);
    cudaGetSymbolAddress((void**)&f1, g_f1);
    cudaGetSymbolAddress((void**)&f2, g_f2);

    dim3 tb(256);
    dim3 gD(DD / 64, NN / 64);        // Nn=256
    dim3 gF1(2 * DD / 64, NN / 64);   // Nn=512

    // QKV projections
    gemm_bias_kernel<<<gD, tb>>>(x, Wq, bq, q, NN, DD, DD, 0);
    gemm_bias_kernel<<<gD, tb>>>(x, Wk, bk, k, NN, DD, DD, 0);
    gemm_bias_kernel<<<gD, tb>>>(x, Wv, bv, v, NN, DD, DD, 0);

    // masked attention
    attn_kernel<<<dim3(NN / 128, HH), 128>>>(q, k, v, adj, o);

    // output projection + LN1
    gemm_bias_kernel<<<gD, tb>>>(o, Wo, bo, h, NN, DD, DD, 0);
    ln_kernel<<<NN, DD>>>(h, x, g1, be1, x1);

    // FFN
    gemm_bias_kernel<<<gF1, tb>>>(x1, W1, b1, f1, NN, 2 * DD, DD, 1);
    gemm_bias_kernel<<<gD, tb>>>(f1, W2, b2, f2, NN, DD, 2 * DD, 0);

    // LN2 -> final output
    ln_kernel<<<NN, DD>>>(f2, x1, g2, be2, out);
}

// round 7
// speedup vs baseline: 1.2095x; 1.2095x over previous
#include <cuda_runtime.h>
#include <math.h>

#define NN 4096
#define DD 256
#define HH 8
#define HDIM 32
#define EPS 1e-5f
#define KSPLIT 8
#define KCHUNK (NN / KSPLIT)   // 512

// ---------------- scratch (device globals: allocation-free) ----------------
__device__ float g_q[NN * DD];
__device__ float g_k[NN * DD];
__device__ float g_v[NN * DD];
__device__ float g_o[NN * DD];   // attention output (pre-Wo)
__device__ float g_h[NN * DD];   // o @ Wo^T + bo
__device__ float g_x1[NN * DD];  // after first LN
__device__ float g_f1[NN * 2 * DD];
__device__ float g_f2[NN * DD];
__device__ float g_pacc[KSPLIT * NN * DD];      // split-K partial numerators
__device__ float g_pl[KSPLIT * NN * HH];        // split-K partial denominators

// ---------------- GEMM: C[M,Nn] = A[M,K] @ B[Nn,K]^T + bias, opt relu ------
__global__ void gemm_bias_kernel(const float* __restrict__ A,
                                 const float* __restrict__ B,
                                 const float* __restrict__ bias,
                                 float* __restrict__ C,
                                 int M, int Nn, int K, int relu) {
    __shared__ float As[16][64];
    __shared__ float Bs[16][64];

    const int tid = threadIdx.x;
    const int m0 = blockIdx.y * 64;
    const int n0 = blockIdx.x * 64;

    const int lrow = tid >> 2;
    const int lkq  = tid & 3;

    const int tm = (tid >> 4) * 4;
    const int tn = (tid & 15) * 4;

    float acc[4][4];
#pragma unroll
    for (int i = 0; i < 4; i++)
#pragma unroll
        for (int j = 0; j < 4; j++) acc[i][j] = 0.f;

    for (int k0 = 0; k0 < K; k0 += 16) {
        float4 a4 = *reinterpret_cast<const float4*>(A + (size_t)(m0 + lrow) * K + k0 + lkq * 4);
        float4 b4 = *reinterpret_cast<const float4*>(B + (size_t)(n0 + lrow) * K + k0 + lkq * 4);
        As[lkq * 4 + 0][lrow] = a4.x;
        As[lkq * 4 + 1][lrow] = a4.y;
        As[lkq * 4 + 2][lrow] = a4.z;
        As[lkq * 4 + 3][lrow] = a4.w;
        Bs[lkq * 4 + 0][lrow] = b4.x;
        Bs[lkq * 4 + 1][lrow] = b4.y;
        Bs[lkq * 4 + 2][lrow] = b4.z;
        Bs[lkq * 4 + 3][lrow] = b4.w;
        __syncthreads();

#pragma unroll
        for (int k = 0; k < 16; k++) {
            float4 av = *reinterpret_cast<const float4*>(&As[k][tm]);
            float4 bv = *reinterpret_cast<const float4*>(&Bs[k][tn]);
            float ar[4] = {av.x, av.y, av.z, av.w};
            float br[4] = {bv.x, bv.y, bv.z, bv.w};
#pragma unroll
            for (int i = 0; i < 4; i++)
#pragma unroll
                for (int j = 0; j < 4; j++)
                    acc[i][j] = fmaf(ar[i], br[j], acc[i][j]);
        }
        __syncthreads();
    }

#pragma unroll
    for (int i = 0; i < 4; i++) {
        int row = m0 + tm + i;
#pragma unroll
        for (int j = 0; j < 4; j++) {
            int col = n0 + tn + j;
            float v = acc[i][j] + bias[col];
            if (relu) v = fmaxf(v, 0.f);
            C[(size_t)row * Nn + col] = v;
        }
    }
}

// ---------------- masked attention, split-K partials ----------------------
// grid: (NN/256, HH, KSPLIT), 128 threads; thread owns TWO query rows.
// No online max: scores are tightly bounded (|s| < ~3), plain exp2 sums.
__global__ void attn_part_kernel(const float* __restrict__ q,
                                 const float* __restrict__ k,
                                 const float* __restrict__ v,
                                 const int* __restrict__ adj,
                                 float* __restrict__ pacc,
                                 float* __restrict__ pl) {
    const int h     = blockIdx.y;
    const int split = blockIdx.z;
    const int tid   = threadIdx.x;
    const int r0    = blockIdx.x * 256 + tid;
    const int r1    = r0 + 128;

    __shared__ float Ks[32][HDIM];
    __shared__ float Vs[32][HDIM];

    // scale * log2(e): fold softmax scale and exp->exp2 conversion into q
    const float sc = 0.17677669529663687f * 1.4426950408889634f;

    float qa[HDIM], qb[HDIM];
    {
        const float* qp0 = q + (size_t)r0 * DD + h * HDIM;
        const float* qp1 = q + (size_t)r1 * DD + h * HDIM;
#pragma unroll
        for (int e = 0; e < HDIM; e++) { qa[e] = qp0[e] * sc; qb[e] = qp1[e] * sc; }
    }

    float acc0[HDIM], acc1[HDIM];
#pragma unroll
    for (int e = 0; e < HDIM; e++) { acc0[e] = 0.f; acc1[e] = 0.f; }
    float l0 = 0.f, l1 = 0.f;

    const int key0 = split * KCHUNK;

    for (int c0 = key0; c0 < key0 + KCHUNK; c0 += 32) {
        __syncthreads();
#pragma unroll
        for (int i = tid; i < 256; i += 128) {
            int row = i >> 3, c4 = i & 7;
            reinterpret_cast<float4*>(&Ks[row][0])[c4] =
                reinterpret_cast<const float4*>(k + (size_t)(c0 + row) * DD + h * HDIM)[c4];
            reinterpret_cast<float4*>(&Vs[row][0])[c4] =
                reinterpret_cast<const float4*>(v + (size_t)(c0 + row) * DD + h * HDIM)[c4];
        }
        __syncthreads();

        // adjacency bitmasks for both query rows over this 32-key tile
        unsigned mb0 = 0, mb1 = 0;
        {
            const int4* a0 = reinterpret_cast<const int4*>(adj + (size_t)r0 * NN + c0);
            const int4* a1 = reinterpret_cast<const int4*>(adj + (size_t)r1 * NN + c0);
#pragma unroll
            for (int j = 0; j < 8; j++) {
                int4 a = a0[j];
                int base = j * 4;
                mb0 |= (unsigned)(a.x != 0) << (base + 0);
                mb0 |= (unsigned)(a.y != 0) << (base + 1);
                mb0 |= (unsigned)(a.z != 0) << (base + 2);
                mb0 |= (unsigned)(a.w != 0) << (base + 3);
                int4 b = a1[j];
                mb1 |= (unsigned)(b.x != 0) << (base + 0);
                mb1 |= (unsigned)(b.y != 0) << (base + 1);
                mb1 |= (unsigned)(b.z != 0) << (base + 2);
                mb1 |= (unsigned)(b.w != 0) << (base + 3);
            }
            // self-loops
            if ((unsigned)(r0 - c0) < 32u) mb0 |= 1u << (r0 - c0);
            if ((unsigned)(r1 - c0) < 32u) mb1 |= 1u << (r1 - c0);
        }

#pragma unroll
        for (int cc = 0; cc < 32; cc++) {
            // K row (broadcast LDS.128)
            const float4* kp = reinterpret_cast<const float4*>(&Ks[cc][0]);
            float d0a = 0.f, d0b = 0.f, d1a = 0.f, d1b = 0.f;
#pragma unroll
            for (int e8 = 0; e8 < 8; e8 += 2) {
                float4 k0v = kp[e8];
                float4 k1v = kp[e8 + 1];
                int ebase = e8 * 4;
                d0a = fmaf(qa[ebase + 0], k0v.x, d0a);
                d0a = fmaf(qa[ebase + 1], k0v.y, d0a);
                d0a = fmaf(qa[ebase + 2], k0v.z, d0a);
                d0a = fmaf(qa[ebase + 3], k0v.w, d0a);
                d0b = fmaf(qa[ebase + 4], k1v.x, d0b);
                d0b = fmaf(qa[ebase + 5], k1v.y, d0b);
                d0b = fmaf(qa[ebase + 6], k1v.z, d0b);
                d0b = fmaf(qa[ebase + 7], k1v.w, d0b);
                d1a = fmaf(qb[ebase + 0], k0v.x, d1a);
                d1a = fmaf(qb[ebase + 1], k0v.y, d1a);
                d1a = fmaf(qb[ebase + 2], k0v.z, d1a);
                d1a = fmaf(qb[ebase + 3], k0v.w, d1a);
                d1b = fmaf(qb[ebase + 4], k1v.x, d1b);
                d1b = fmaf(qb[ebase + 5], k1v.y, d1b);
                d1b = fmaf(qb[ebase + 6], k1v.z, d1b);
                d1b = fmaf(qb[ebase + 7], k1v.w, d1b);
            }
            float bias0 = ((mb0 >> cc) & 1u) ? 0.f : -64.f;
            float bias1 = ((mb1 >> cc) & 1u) ? 0.f : -64.f;
            float p0 = exp2f(d0a + d0b + bias0);
            float p1 = exp2f(d1a + d1b + bias1);
            l0 += p0;
            l1 += p1;

            const float4* vp = reinterpret_cast<const float4*>(&Vs[cc][0]);
#pragma unroll
            for (int e8 = 0; e8 < 8; e8++) {
                float4 vv = vp[e8];
                int ebase = e8 * 4;
                acc0[ebase + 0] = fmaf(p0, vv.x, acc0[ebase + 0]);
                acc0[ebase + 1] = fmaf(p0, vv.y, acc0[ebase + 1]);
                acc0[ebase + 2] = fmaf(p0, vv.z, acc0[ebase + 2]);
                acc0[ebase + 3] = fmaf(p0, vv.w, acc0[ebase + 3]);
                acc1[ebase + 0] = fmaf(p1, vv.x, acc1[ebase + 0]);
                acc1[ebase + 1] = fmaf(p1, vv.y, acc1[ebase + 1]);
                acc1[ebase + 2] = fmaf(p1, vv.z, acc1[ebase + 2]);
                acc1[ebase + 3] = fmaf(p1, vv.w, acc1[ebase + 3]);
            }
        }
    }

    // write partials
    float* pa0 = pacc + ((size_t)split * NN + r0) * DD + h * HDIM;
    float* pa1 = pacc + ((size_t)split * NN + r1) * DD + h * HDIM;
#pragma unroll
    for (int e8 = 0; e8 < 8; e8++) {
        reinterpret_cast<float4*>(pa0)[e8] =
            make_float4(acc0[e8 * 4 + 0], acc0[e8 * 4 + 1], acc0[e8 * 4 + 2], acc0[e8 * 4 + 3]);
        reinterpret_cast<float4*>(pa1)[e8] =
            make_float4(acc1[e8 * 4 + 0], acc1[e8 * 4 + 1], acc1[e8 * 4 + 2], acc1[e8 * 4 + 3]);
    }
    pl[((size_t)split * NN + r0) * HH + h] = l0;
    pl[((size_t)split * NN + r1) * HH + h] = l1;
}

// ---------------- split-K reduce: o = sum(acc)/sum(l) ---------------------
__global__ void attn_reduce_kernel(const float* __restrict__ pacc,
                                   const float* __restrict__ pl,
                                   float* __restrict__ o) {
    const int r = blockIdx.x;
    const int t = threadIdx.x;       // feature index 0..255
    const int h = t >> 5;

    float s = 0.f;
#pragma unroll
    for (int sp = 0; sp < KSPLIT; sp++)
        s += pacc[((size_t)sp * NN + r) * DD + t];

    float L = 0.f;
#pragma unroll
    for (int sp = 0; sp < KSPLIT; sp++)
        L += pl[((size_t)sp * NN + r) * HH + h];

    o[(size_t)r * DD + t] = s / L;
}

// ---------------- residual add + layernorm -------------------------------
__global__ void ln_kernel(const float* __restrict__ a,
                          const float* __restrict__ res,
                          const float* __restrict__ g,
                          const float* __restrict__ beta,
                          float* __restrict__ out) {
    const int row = blockIdx.x;
    const int t = threadIdx.x;
    const int lane = t & 31, warp = t >> 5;

    float x = a[(size_t)row * DD + t] + res[(size_t)row * DD + t];
    float s = x, s2 = x * x;
#pragma unroll
    for (int off = 16; off; off >>= 1) {
        s  += __shfl_xor_sync(0xffffffffu, s, off);
        s2 += __shfl_xor_sync(0xffffffffu, s2, off);
    }
    __shared__ float sh[2][8];
    if (lane == 0) { sh[0][warp] = s; sh[1][warp] = s2; }
    __syncthreads();
    float S = 0.f, S2 = 0.f;
#pragma unroll
    for (int i = 0; i < 8; i++) { S += sh[0][i]; S2 += sh[1][i]; }

    float mu = S * (1.0f / DD);
    float var = S2 * (1.0f / DD) - mu * mu;
    float r = rsqrtf(var + EPS);
    out[(size_t)row * DD + t] = (x - mu) * r * g[t] + beta[t];
}

// ---------------- launch --------------------------------------------------
extern "C" void kernel_launch(void* const* d_in, const int* in_sizes, int n_in,
                              void* d_out, int out_size) {
    const float* x    = (const float*)d_in[0];
    const int*   adj  = (const int*)d_in[1];
    const float* Wq   = (const float*)d_in[2];
    const float* Wk   = (const float*)d_in[3];
    const float* Wv   = (const float*)d_in[4];
    const float* bq   = (const float*)d_in[5];
    const float* bk   = (const float*)d_in[6];
    const float* bv   = (const float*)d_in[7];
    const float* Wo   = (const float*)d_in[8];
    const float* bo   = (const float*)d_in[9];
    const float* g1   = (const float*)d_in[10];
    const float* be1  = (const float*)d_in[11];
    const float* W1   = (const float*)d_in[12];
    const float* b1   = (const float*)d_in[13];
    const float* W2   = (const float*)d_in[14];
    const float* b2   = (const float*)d_in[15];
    const float* g2   = (const float*)d_in[16];
    const float* be2  = (const float*)d_in[17];
    float* out = (float*)d_out;

    float *q, *k, *v, *o, *h, *x1, *f1, *f2, *pacc, *pl;
    cudaGetSymbolAddress((void**)&q,    g_q);
    cudaGetSymbolAddress((void**)&k,    g_k);
    cudaGetSymbolAddress((void**)&v,    g_v);
    cudaGetSymbolAddress((void**)&o,    g_o);
    cudaGetSymbolAddress((void**)&h,    g_h);
    cudaGetSymbolAddress((void**)&x1,   g_x1);
    cudaGetSymbolAddress((void**)&f1,   g_f1);
    cudaGetSymbolAddress((void**)&f2,   g_f2);
    cudaGetSymbolAddress((void**)&pacc, g_pacc);
    cudaGetSymbolAddress((void**)&pl,   g_pl);

    dim3 tb(256);
    dim3 gD(DD / 64, NN / 64);        // Nn=256
    dim3 gF1(2 * DD / 64, NN / 64);   // Nn=512

    // QKV projections
    gemm_bias_kernel<<<gD, tb>>>(x, Wq, bq, q, NN, DD, DD, 0);
    gemm_bias_kernel<<<gD, tb>>>(x, Wk, bk, k, NN, DD, DD, 0);
    gemm_bias_kernel<<<gD, tb>>>(x, Wv, bv, v, NN, DD, DD, 0);

    // masked attention: split-K partials + reduce
    attn_part_kernel<<<dim3(NN / 256, HH, KSPLIT), 128>>>(q, k, v, adj, pacc, pl);
    attn_reduce_kernel<<<NN, DD>>>(pacc, pl, o);

    // output projection + LN1
    gemm_bias_kernel<<<gD, tb>>>(o, Wo, bo, h, NN, DD, DD, 0);
    ln_kernel<<<NN, DD>>>(h, x, g1, be1, x1);

    // FFN
    gemm_bias_kernel<<<gF1, tb>>>(x1, W1, b1, f1, NN, 2 * DD, DD, 1);
    gemm_bias_kernel<<<gD, tb>>>(f1, W2, b2, f2, NN, DD, 2 * DD, 0);

    // LN2 -> final output
    ln_kernel<<<NN, DD>>>(f2, x1, g2, be2, out);
}

// round 10
// speedup vs baseline: 3.3749x; 2.7904x over previous
#include <cuda_runtime.h>
#include <cuda_bf16.h>
#include <math.h>

#define NN 4096
#define DD 256
#define HH 8
#define HDIM 32
#define EPS 1e-5f
#define KSPLIT 2
#define KCHUNK (NN / KSPLIT)    // 2048
#define KSTRIDE 40              // Ks smem row stride (bf16): 80B = 5*16, conflict-free
#define VTSTRIDE 72             // Vs smem row stride (bf16): 144B = 9*16, conflict-free

// ---------------- scratch (device globals: allocation-free) ----------------
__device__ float          g_v[NN * DD];
__device__ __nv_bfloat16  g_qb[NN * DD];
__device__ __nv_bfloat16  g_kb[NN * DD];       // pre-scaled by scale*log2(e)
__device__ __nv_bfloat16  g_vt[DD * NN];       // V transposed: [d][n]
__device__ unsigned       g_mbits[NN * (NN / 32)];
__device__ float          g_o[NN * DD];
__device__ float          g_h[NN * DD];
__device__ float          g_x1[NN * DD];
__device__ float          g_f1[NN * 2 * DD];
__device__ float          g_f2[NN * DD];
__device__ float          g_pacc[KSPLIT * NN * DD];
__device__ float          g_pl[KSPLIT * NN * HH];

// ---------------- small PTX helpers ---------------------------------------
__device__ __forceinline__ float ex2(float x) {
    float r;
    asm("ex2.approx.ftz.f32 %0, %1;" : "=f"(r) : "f"(x));
    return r;
}
__device__ __forceinline__ unsigned packbf(float lo, float hi) {
    unsigned r;
    asm("cvt.rn.bf16x2.f32 %0, %1, %2;" : "=r"(r) : "f"(hi), "f"(lo));
    return r;
}
__device__ __forceinline__ void mma_bf16(float c[4], unsigned a0, unsigned a1,
                                         unsigned a2, unsigned a3,
                                         unsigned b0, unsigned b1) {
    asm("mma.sync.aligned.m16n8k16.row.col.f32.bf16.bf16.f32 "
        "{%0,%1,%2,%3},{%4,%5,%6,%7},{%8,%9},{%0,%1,%2,%3};"
        : "+f"(c[0]), "+f"(c[1]), "+f"(c[2]), "+f"(c[3])
        : "r"(a0), "r"(a1), "r"(a2), "r"(a3), "r"(b0), "r"(b1));
}

// ---------------- GEMM fp32: C = A@B^T + bias, opt relu -------------------
__global__ void gemm_bias_kernel(const float* __restrict__ A,
                                 const float* __restrict__ B,
                                 const float* __restrict__ bias,
                                 float* __restrict__ C,
                                 int M, int Nn, int K, int relu) {
    __shared__ float As[16][64];
    __shared__ float Bs[16][64];

    const int tid = threadIdx.x;
    const int m0 = blockIdx.y * 64;
    const int n0 = blockIdx.x * 64;
    const int lrow = tid >> 2;
    const int lkq  = tid & 3;
    const int tm = (tid >> 4) * 4;
    const int tn = (tid & 15) * 4;

    float acc[4][4];
#pragma unroll
    for (int i = 0; i < 4; i++)
#pragma unroll
        for (int j = 0; j < 4; j++) acc[i][j] = 0.f;

    for (int k0 = 0; k0 < K; k0 += 16) {
        float4 a4 = *reinterpret_cast<const float4*>(A + (size_t)(m0 + lrow) * K + k0 + lkq * 4);
        float4 b4 = *reinterpret_cast<const float4*>(B + (size_t)(n0 + lrow) * K + k0 + lkq * 4);
        As[lkq * 4 + 0][lrow] = a4.x; As[lkq * 4 + 1][lrow] = a4.y;
        As[lkq * 4 + 2][lrow] = a4.z; As[lkq * 4 + 3][lrow] = a4.w;
        Bs[lkq * 4 + 0][lrow] = b4.x; Bs[lkq * 4 + 1][lrow] = b4.y;
        Bs[lkq * 4 + 2][lrow] = b4.z; Bs[lkq * 4 + 3][lrow] = b4.w;
        __syncthreads();
#pragma unroll
        for (int k = 0; k < 16; k++) {
            float4 av = *reinterpret_cast<const float4*>(&As[k][tm]);
            float4 bv = *reinterpret_cast<const float4*>(&Bs[k][tn]);
            float ar[4] = {av.x, av.y, av.z, av.w};
            float br[4] = {bv.x, bv.y, bv.z, bv.w};
#pragma unroll
            for (int i = 0; i < 4; i++)
#pragma unroll
                for (int j = 0; j < 4; j++)
                    acc[i][j] = fmaf(ar[i], br[j], acc[i][j]);
        }
        __syncthreads();
    }
#pragma unroll
    for (int i = 0; i < 4; i++) {
        int row = m0 + tm + i;
#pragma unroll
        for (int j = 0; j < 4; j++) {
            int col = n0 + tn + j;
            float v = acc[i][j] + bias[col];
            if (relu) v = fmaxf(v, 0.f);
            C[(size_t)row * Nn + col] = v;
        }
    }
}

// ---------------- GEMM with bf16 output (+scale) for Q/K -------------------
__global__ void gemm_bias_bf16_kernel(const float* __restrict__ A,
                                      const float* __restrict__ B,
                                      const float* __restrict__ bias,
                                      __nv_bfloat16* __restrict__ C,
                                      int M, int Nn, int K, float outscale) {
    __shared__ float As[16][64];
    __shared__ float Bs[16][64];

    const int tid = threadIdx.x;
    const int m0 = blockIdx.y * 64;
    const int n0 = blockIdx.x * 64;
    const int lrow = tid >> 2;
    const int lkq  = tid & 3;
    const int tm = (tid >> 4) * 4;
    const int tn = (tid & 15) * 4;

    float acc[4][4];
#pragma unroll
    for (int i = 0; i < 4; i++)
#pragma unroll
        for (int j = 0; j < 4; j++) acc[i][j] = 0.f;

    for (int k0 = 0; k0 < K; k0 += 16) {
        float4 a4 = *reinterpret_cast<const float4*>(A + (size_t)(m0 + lrow) * K + k0 + lkq * 4);
        float4 b4 = *reinterpret_cast<const float4*>(B + (size_t)(n0 + lrow) * K + k0 + lkq * 4);
        As[lkq * 4 + 0][lrow] = a4.x; As[lkq * 4 + 1][lrow] = a4.y;
        As[lkq * 4 + 2][lrow] = a4.z; As[lkq * 4 + 3][lrow] = a4.w;
        Bs[lkq * 4 + 0][lrow] = b4.x; Bs[lkq * 4 + 1][lrow] = b4.y;
        Bs[lkq * 4 + 2][lrow] = b4.z; Bs[lkq * 4 + 3][lrow] = b4.w;
        __syncthreads();
#pragma unroll
        for (int k = 0; k < 16; k++) {
            float4 av = *reinterpret_cast<const float4*>(&As[k][tm]);
            float4 bv = *reinterpret_cast<const float4*>(&Bs[k][tn]);
            float ar[4] = {av.x, av.y, av.z, av.w};
            float br[4] = {bv.x, bv.y, bv.z, bv.w};
#pragma unroll
            for (int i = 0; i < 4; i++)
#pragma unroll
                for (int j = 0; j < 4; j++)
                    acc[i][j] = fmaf(ar[i], br[j], acc[i][j]);
        }
        __syncthreads();
    }
#pragma unroll
    for (int i = 0; i < 4; i++) {
        int row = m0 + tm + i;
        int col = n0 + tn;
        float v0 = (acc[i][0] + bias[col + 0]) * outscale;
        float v1 = (acc[i][1] + bias[col + 1]) * outscale;
        float v2 = (acc[i][2] + bias[col + 2]) * outscale;
        float v3 = (acc[i][3] + bias[col + 3]) * outscale;
        unsigned* cp = reinterpret_cast<unsigned*>(C + (size_t)row * Nn + col);
        cp[0] = packbf(v0, v1);
        cp[1] = packbf(v2, v3);
    }
}

// ---------------- V transpose fp32 -> bf16 [d][n] --------------------------
__global__ void vtrans_kernel(const float* __restrict__ v,
                              __nv_bfloat16* __restrict__ vt) {
    __shared__ float tile[64][33];
    const int n0 = blockIdx.x * 64;
    const int d0 = blockIdx.y * 32;
    const int t = threadIdx.x;

    for (int i = t; i < 512; i += 256) {
        int row = i >> 3, c = i & 7;
        float4 val = *reinterpret_cast<const float4*>(v + (size_t)(n0 + row) * DD + d0 + c * 4);
        tile[row][c * 4 + 0] = val.x;
        tile[row][c * 4 + 1] = val.y;
        tile[row][c * 4 + 2] = val.z;
        tile[row][c * 4 + 3] = val.w;
    }
    __syncthreads();

    unsigned* vt32 = reinterpret_cast<unsigned*>(vt);
    for (int o = t; o < 1024; o += 256) {
        int d = o >> 5, np = o & 31;
        unsigned pk = packbf(tile[np * 2][d], tile[np * 2 + 1][d]);
        vt32[(size_t)(d0 + d) * (NN / 2) + (n0 >> 1) + np] = pk;
    }
}

// ---------------- adjacency -> bitmask (with self loop) --------------------
__global__ void maskpack_kernel(const int* __restrict__ adj,
                                unsigned* __restrict__ mbits) {
    const int r = blockIdx.x;
    const int t = threadIdx.x;   // word index 0..127
    const int4* ap = reinterpret_cast<const int4*>(adj + (size_t)r * NN + t * 32);
    unsigned m = 0;
#pragma unroll
    for (int j = 0; j < 8; j++) {
        int4 a = ap[j];
        m |= (unsigned)(a.x != 0) << (j * 4 + 0);
        m |= (unsigned)(a.y != 0) << (j * 4 + 1);
        m |= (unsigned)(a.z != 0) << (j * 4 + 2);
        m |= (unsigned)(a.w != 0) << (j * 4 + 3);
    }
    if ((r >> 5) == t) m |= 1u << (r & 31);
    mbits[(size_t)r * (NN / 32) + t] = m;
}

// ---------------- bf16 tensor-core masked attention ------------------------
// grid (NN/64, HH, KSPLIT), 128 threads = 4 warps; warp owns 16 q rows.
__global__ __launch_bounds__(128) void attn_mma_kernel(
    const __nv_bfloat16* __restrict__ qb,
    const __nv_bfloat16* __restrict__ kb,
    const __nv_bfloat16* __restrict__ vt,
    const unsigned* __restrict__ mbits,
    float* __restrict__ pacc, float* __restrict__ pl) {

    const int h = blockIdx.y, split = blockIdx.z;
    const int tid = threadIdx.x;
    const int w = tid >> 5, lane = tid & 31;
    const int g = lane >> 2, tg = lane & 3;
    const int r0 = blockIdx.x * 64;
    const int wr = r0 + w * 16;

    __shared__ alignas(16) __nv_bfloat16 Ks[64 * KSTRIDE];
    __shared__ alignas(16) __nv_bfloat16 Vs[32 * VTSTRIDE];
    __shared__ alignas(16) unsigned Ms[64][2];

    // Q A-fragments: 2 ksteps (d 0..15, 16..31) x 4 regs
    unsigned qa[2][4];
#pragma unroll
    for (int kk = 0; kk < 2; kk++) {
        const __nv_bfloat16* q0 = qb + (size_t)(wr + g) * DD + h * HDIM + kk * 16 + 2 * tg;
        const __nv_bfloat16* q1 = qb + (size_t)(wr + g + 8) * DD + h * HDIM + kk * 16 + 2 * tg;
        qa[kk][0] = *reinterpret_cast<const unsigned*>(q0);
        qa[kk][1] = *reinterpret_cast<const unsigned*>(q1);
        qa[kk][2] = *reinterpret_cast<const unsigned*>(q0 + 8);
        qa[kk][3] = *reinterpret_cast<const unsigned*>(q1 + 8);
    }

    float oc[4][4];
#pragma unroll
    for (int i = 0; i < 4; i++)
#pragma unroll
        for (int j = 0; j < 4; j++) oc[i][j] = 0.f;
    float l0 = 0.f, l1 = 0.f;

    const int kbase = split * KCHUNK;
    for (int c0 = kbase; c0 < kbase + KCHUNK; c0 += 64) {
        __syncthreads();
        // K tile: 64 keys x 32 d (bf16)
        for (int i = tid; i < 256; i += 128) {
            int row = i >> 2, c = i & 3;
            float4 val = *reinterpret_cast<const float4*>(
                kb + (size_t)(c0 + row) * DD + h * HDIM + c * 8);
            *reinterpret_cast<float4*>(Ks + row * KSTRIDE + c * 8) = val;
        }
        // V^T tile: 32 d x 64 keys
        for (int i = tid; i < 256; i += 128) {
            int row = i >> 3, c = i & 7;
            float4 val = *reinterpret_cast<const float4*>(
                vt + (size_t)(h * HDIM + row) * NN + c0 + c * 8);
            *reinterpret_cast<float4*>(Vs + row * VTSTRIDE + c * 8) = val;
        }
        // mask words: 64 rows x 2 words
        {
            int row = tid >> 1, ws = tid & 1;
            Ms[row][ws] = mbits[(size_t)(r0 + row) * (NN / 32) + (c0 >> 5) + ws];
        }
        __syncthreads();

        // ---- S = Q K^T  (16 rows x 64 keys per warp) ----
        float s[8][4];
#pragma unroll
        for (int nt = 0; nt < 8; nt++)
#pragma unroll
            for (int j = 0; j < 4; j++) s[nt][j] = 0.f;
#pragma unroll
        for (int kk = 0; kk < 2; kk++)
#pragma unroll
            for (int nt = 0; nt < 8; nt++) {
                unsigned b0 = *reinterpret_cast<const unsigned*>(
                    Ks + (nt * 8 + g) * KSTRIDE + kk * 16 + 2 * tg);
                unsigned b1 = *reinterpret_cast<const unsigned*>(
                    Ks + (nt * 8 + g) * KSTRIDE + kk * 16 + 2 * tg + 8);
                mma_bf16(s[nt], qa[kk][0], qa[kk][1], qa[kk][2], qa[kk][3], b0, b1);
            }

        // ---- mask + exp2 (scale already folded into kb) ----
        unsigned m0lo = Ms[w * 16 + g][0],     m0hi = Ms[w * 16 + g][1];
        unsigned m1lo = Ms[w * 16 + g + 8][0], m1hi = Ms[w * 16 + g + 8][1];
#pragma unroll
        for (int nt = 0; nt < 8; nt++) {
            unsigned w0 = (nt < 4) ? m0lo : m0hi;
            unsigned w1 = (nt < 4) ? m1lo : m1hi;
            int sh = (nt & 3) * 8 + 2 * tg;
            float p0 = ex2(((w0 >> sh) & 1u)       ? s[nt][0] : -64.f);
            float p1 = ex2(((w0 >> (sh + 1)) & 1u) ? s[nt][1] : -64.f);
            float p2 = ex2(((w1 >> sh) & 1u)       ? s[nt][2] : -64.f);
            float p3 = ex2(((w1 >> (sh + 1)) & 1u) ? s[nt][3] : -64.f);
            l0 += p0 + p1;
            l1 += p2 + p3;
            s[nt][0] = p0; s[nt][1] = p1; s[nt][2] = p2; s[nt][3] = p3;
        }

        // ---- O += P V  (P fragments pack directly from accumulators) ----
#pragma unroll
        for (int kk = 0; kk < 4; kk++) {
            unsigned pa0 = packbf(s[2 * kk][0],     s[2 * kk][1]);
            unsigned pa1 = packbf(s[2 * kk][2],     s[2 * kk][3]);
            unsigned pa2 = packbf(s[2 * kk + 1][0], s[2 * kk + 1][1]);
            unsigned pa3 = packbf(s[2 * kk + 1][2], s[2 * kk + 1][3]);
#pragma unroll
            for (int nd = 0; nd < 4; nd++) {
                unsigned b0 = *reinterpret_cast<const unsigned*>(
                    Vs + (nd * 8 + g) * VTSTRIDE + kk * 16 + 2 * tg);
                unsigned b1 = *reinterpret_cast<const unsigned*>(
                    Vs + (nd * 8 + g) * VTSTRIDE + kk * 16 + 2 * tg + 8);
                mma_bf16(oc[nd], pa0, pa1, pa2, pa3, b0, b1);
            }
        }
    }

    // reduce l across the 4-lane quad (same row)
    l0 += __shfl_xor_sync(0xffffffffu, l0, 1);
    l0 += __shfl_xor_sync(0xffffffffu, l0, 2);
    l1 += __shfl_xor_sync(0xffffffffu, l1, 1);
    l1 += __shfl_xor_sync(0xffffffffu, l1, 2);

    // write UNNORMALIZED numerators; the reduce kernel does the single division
    float* p0 = pacc + ((size_t)split * NN + wr + g) * DD + h * HDIM;
    float* p1 = pacc + ((size_t)split * NN + wr + g + 8) * DD + h * HDIM;
#pragma unroll
    for (int nd = 0; nd < 4; nd++) {
        int col = nd * 8 + 2 * tg;
        *reinterpret_cast<float2*>(p0 + col) = make_float2(oc[nd][0], oc[nd][1]);
        *reinterpret_cast<float2*>(p1 + col) = make_float2(oc[nd][2], oc[nd][3]);
    }
    if (tg == 0) {
        pl[((size_t)split * NN + wr + g) * HH + h] = l0;
        pl[((size_t)split * NN + wr + g + 8) * HH + h] = l1;
    }
}

// ---------------- split-K reduce ------------------------------------------
__global__ void attn_reduce_kernel(const float* __restrict__ pacc,
                                   const float* __restrict__ pl,
                                   float* __restrict__ o) {
    const int r = blockIdx.x;
    const int t = threadIdx.x;
    const int h = t >> 5;
    float s = 0.f;
#pragma unroll
    for (int sp = 0; sp < KSPLIT; sp++)
        s += pacc[((size_t)sp * NN + r) * DD + t];
    float L = 0.f;
#pragma unroll
    for (int sp = 0; sp < KSPLIT; sp++)
        L += pl[((size_t)sp * NN + r) * HH + h];
    o[(size_t)r * DD + t] = s / L;
}

// ---------------- residual add + layernorm -------------------------------
__global__ void ln_kernel(const float* __restrict__ a,
                          const float* __restrict__ res,
                          const float* __restrict__ g,
                          const float* __restrict__ beta,
                          float* __restrict__ out) {
    const int row = blockIdx.x;
    const int t = threadIdx.x;
    const int lane = t & 31, warp = t >> 5;

    float x = a[(size_t)row * DD + t] + res[(size_t)row * DD + t];
    float s = x, s2 = x * x;
#pragma unroll
    for (int off = 16; off; off >>= 1) {
        s  += __shfl_xor_sync(0xffffffffu, s, off);
        s2 += __shfl_xor_sync(0xffffffffu, s2, off);
    }
    __shared__ float sh[2][8];
    if (lane == 0) { sh[0][warp] = s; sh[1][warp] = s2; }
    __syncthreads();
    float S = 0.f, S2 = 0.f;
#pragma unroll
    for (int i = 0; i < 8; i++) { S += sh[0][i]; S2 += sh[1][i]; }

    float mu = S * (1.0f / DD);
    float var = S2 * (1.0f / DD) - mu * mu;
    float r = rsqrtf(var + EPS);
    out[(size_t)row * DD + t] = (x - mu) * r * g[t] + beta[t];
}

// ---------------- launch --------------------------------------------------
extern "C" void kernel_launch(void* const* d_in, const int* in_sizes, int n_in,
                              void* d_out, int out_size) {
    const float* x    = (const float*)d_in[0];
    const int*   adj  = (const int*)d_in[1];
    const float* Wq   = (const float*)d_in[2];
    const float* Wk   = (const float*)d_in[3];
    const float* Wv   = (const float*)d_in[4];
    const float* bq   = (const float*)d_in[5];
    const float* bk   = (const float*)d_in[6];
    const float* bv   = (const float*)d_in[7];
    const float* Wo   = (const float*)d_in[8];
    const float* bo   = (const float*)d_in[9];
    const float* g1   = (const float*)d_in[10];
    const float* be1  = (const float*)d_in[11];
    const float* W1   = (const float*)d_in[12];
    const float* b1   = (const float*)d_in[13];
    const float* W2   = (const float*)d_in[14];
    const float* b2   = (const float*)d_in[15];
    const float* g2   = (const float*)d_in[16];
    const float* be2  = (const float*)d_in[17];
    float* out = (float*)d_out;

    float *v, *o, *h, *x1, *f1, *f2, *pacc, *pl;
    __nv_bfloat16 *qb, *kb, *vt;
    unsigned *mbits;
    cudaGetSymbolAddress((void**)&v,     g_v);
    cudaGetSymbolAddress((void**)&qb,    g_qb);
    cudaGetSymbolAddress((void**)&kb,    g_kb);
    cudaGetSymbolAddress((void**)&vt,    g_vt);
    cudaGetSymbolAddress((void**)&mbits, g_mbits);
    cudaGetSymbolAddress((void**)&o,     g_o);
    cudaGetSymbolAddress((void**)&h,     g_h);
    cudaGetSymbolAddress((void**)&x1,    g_x1);
    cudaGetSymbolAddress((void**)&f1,    g_f1);
    cudaGetSymbolAddress((void**)&f2,    g_f2);
    cudaGetSymbolAddress((void**)&pacc,  g_pacc);
    cudaGetSymbolAddress((void**)&pl,    g_pl);

    const float scl = 0.17677669529663687f * 1.4426950408889634f; // 1/sqrt(32)*log2(e)

    dim3 tb(256);
    dim3 gD(DD / 64, NN / 64);
    dim3 gF1(2 * DD / 64, NN / 64);

    // mask pack (independent of projections)
    maskpack_kernel<<<NN, NN / 32>>>(adj, mbits);

    // QKV projections (q,k -> bf16; k pre-scaled; v -> fp32 then transposed bf16)
    gemm_bias_bf16_kernel<<<gD, tb>>>(x, Wq, bq, qb, NN, DD, DD, 1.0f);
    gemm_bias_bf16_kernel<<<gD, tb>>>(x, Wk, bk, kb, NN, DD, DD, scl);
    gemm_bias_kernel<<<gD, tb>>>(x, Wv, bv, v, NN, DD, DD, 0);
    vtrans_kernel<<<dim3(NN / 64, DD / 32), 256>>>(v, vt);

    // tensor-core masked attention (split-K) + reduce
    attn_mma_kernel<<<dim3(NN / 64, HH, KSPLIT), 128>>>(qb, kb, vt, mbits, pacc, pl);
    attn_reduce_kernel<<<NN, DD>>>(pacc, pl, o);

    // output projection + LN1
    gemm_bias_kernel<<<gD, tb>>>(o, Wo, bo, h, NN, DD, DD, 0);
    ln_kernel<<<NN, DD>>>(h, x, g1, be1, x1);

    // FFN
    gemm_bias_kernel<<<gF1, tb>>>(x1, W1, b1, f1, NN, 2 * DD, DD, 1);
    gemm_bias_kernel<<<gD, tb>>>(f1, W2, b2, f2, NN, DD, 2 * DD, 0);

    // LN2 -> final output
    ln_kernel<<<NN, DD>>>(f2, x1, g2, be2, out);
}

// round 11
// speedup vs baseline: 4.5676x; 1.3534x over previous
#include <cuda_runtime.h>
#include <cuda_bf16.h>
#include <math.h>

#define NN 4096
#define DD 256
#define HH 8
#define HDIM 32
#define EPS 1e-5f
#define KSPLIT 2
#define KCHUNK (NN / KSPLIT)    // 2048
#define KSTRIDE 40              // attn Ks smem row stride (bf16): 80B = 5*16
#define VTSTRIDE 72             // attn Vs smem row stride (bf16): 144B = 9*16
#define GSTRIDE 20              // gemm smem row stride (words): conflict-free for quad pattern

// ---------------- scratch (device globals: allocation-free) ----------------
__device__ float          g_v[NN * DD];
__device__ __nv_bfloat16  g_qb[NN * DD];
__device__ __nv_bfloat16  g_kb[NN * DD];       // pre-scaled by scale*log2(e)
__device__ __nv_bfloat16  g_vt[DD * NN];       // V transposed: [d][n]
__device__ unsigned       g_mbits[NN * (NN / 32)];
__device__ float          g_o[NN * DD];
__device__ float          g_h[NN * DD];
__device__ float          g_x1[NN * DD];
__device__ float          g_f1[NN * 2 * DD];
__device__ float          g_f2[NN * DD];
__device__ float          g_pacc[KSPLIT * NN * DD];
__device__ float          g_pl[KSPLIT * NN * HH];

// ---------------- small PTX helpers ---------------------------------------
__device__ __forceinline__ float ex2(float x) {
    float r;
    asm("ex2.approx.ftz.f32 %0, %1;" : "=f"(r) : "f"(x));
    return r;
}
__device__ __forceinline__ unsigned packbf(float lo, float hi) {
    unsigned r;
    asm("cvt.rn.bf16x2.f32 %0, %1, %2;" : "=r"(r) : "f"(hi), "f"(lo));
    return r;
}
__device__ __forceinline__ unsigned tf32(float x) {
    unsigned r;
    asm("cvt.rna.tf32.f32 %0, %1;" : "=r"(r) : "f"(x));
    return r;
}
__device__ __forceinline__ void mma_bf16(float c[4], unsigned a0, unsigned a1,
                                         unsigned a2, unsigned a3,
                                         unsigned b0, unsigned b1) {
    asm("mma.sync.aligned.m16n8k16.row.col.f32.bf16.bf16.f32 "
        "{%0,%1,%2,%3},{%4,%5,%6,%7},{%8,%9},{%0,%1,%2,%3};"
        : "+f"(c[0]), "+f"(c[1]), "+f"(c[2]), "+f"(c[3])
        : "r"(a0), "r"(a1), "r"(a2), "r"(a3), "r"(b0), "r"(b1));
}
__device__ __forceinline__ void mma_tf32(float c[4], unsigned a0, unsigned a1,
                                         unsigned a2, unsigned a3,
                                         unsigned b0, unsigned b1) {
    asm("mma.sync.aligned.m16n8k8.row.col.f32.tf32.tf32.f32 "
        "{%0,%1,%2,%3},{%4,%5,%6,%7},{%8,%9},{%0,%1,%2,%3};"
        : "+f"(c[0]), "+f"(c[1]), "+f"(c[2]), "+f"(c[3])
        : "r"(a0), "r"(a1), "r"(a2), "r"(a3), "r"(b0), "r"(b1));
}

// ---------------- tf32 tensor-core GEMM: C = A@B^T + bias ------------------
// mode 0: fp32 out; 1: fp32+relu; 2: bf16 out with scale folded
// BM=BN=64, BK=16, 128 threads = 4 warps (2x2), warp tile 32x32.
__global__ __launch_bounds__(128) void gemm_tf32_kernel(
    const float* __restrict__ A, const float* __restrict__ B,
    const float* __restrict__ bias, void* __restrict__ Cout,
    int M, int Nn, int K, int mode, float outscale) {

    __shared__ alignas(16) unsigned As[64 * GSTRIDE];
    __shared__ alignas(16) unsigned Bs[64 * GSTRIDE];

    const int tid = threadIdx.x;
    const int w = tid >> 5, lane = tid & 31;
    const int g = lane >> 2, tg = lane & 3;
    const int m0 = blockIdx.y * 64, n0 = blockIdx.x * 64;
    const int wm = (w >> 1) * 32;
    const int wn = (w & 1) * 32;

    // tile-load mapping: thread -> (row, col8)
    const int lr = tid >> 1;
    const int lc = (tid & 1) * 8;

    float c[2][4][4];
#pragma unroll
    for (int mt = 0; mt < 2; mt++)
#pragma unroll
        for (int nt = 0; nt < 4; nt++)
#pragma unroll
            for (int j = 0; j < 4; j++) c[mt][nt][j] = 0.f;

    for (int k0 = 0; k0 < K; k0 += 16) {
        float4 av0 = *reinterpret_cast<const float4*>(A + (size_t)(m0 + lr) * K + k0 + lc);
        float4 av1 = *reinterpret_cast<const float4*>(A + (size_t)(m0 + lr) * K + k0 + lc + 4);
        float4 bv0 = *reinterpret_cast<const float4*>(B + (size_t)(n0 + lr) * K + k0 + lc);
        float4 bv1 = *reinterpret_cast<const float4*>(B + (size_t)(n0 + lr) * K + k0 + lc + 4);
        uint4 au0 = make_uint4(tf32(av0.x), tf32(av0.y), tf32(av0.z), tf32(av0.w));
        uint4 au1 = make_uint4(tf32(av1.x), tf32(av1.y), tf32(av1.z), tf32(av1.w));
        uint4 bu0 = make_uint4(tf32(bv0.x), tf32(bv0.y), tf32(bv0.z), tf32(bv0.w));
        uint4 bu1 = make_uint4(tf32(bv1.x), tf32(bv1.y), tf32(bv1.z), tf32(bv1.w));
        __syncthreads();
        *reinterpret_cast<uint4*>(As + lr * GSTRIDE + lc)     = au0;
        *reinterpret_cast<uint4*>(As + lr * GSTRIDE + lc + 4) = au1;
        *reinterpret_cast<uint4*>(Bs + lr * GSTRIDE + lc)     = bu0;
        *reinterpret_cast<uint4*>(Bs + lr * GSTRIDE + lc + 4) = bu1;
        __syncthreads();

#pragma unroll
        for (int kk = 0; kk < 2; kk++) {
            const int kb = kk * 8;
            unsigned a[2][4];
#pragma unroll
            for (int mt = 0; mt < 2; mt++) {
                const unsigned* ap0 = As + (wm + mt * 16 + g) * GSTRIDE + kb + tg;
                const unsigned* ap1 = As + (wm + mt * 16 + g + 8) * GSTRIDE + kb + tg;
                a[mt][0] = ap0[0];
                a[mt][1] = ap1[0];
                a[mt][2] = ap0[4];
                a[mt][3] = ap1[4];
            }
#pragma unroll
            for (int nt = 0; nt < 4; nt++) {
                const unsigned* bp = Bs + (wn + nt * 8 + g) * GSTRIDE + kb + tg;
                unsigned b0 = bp[0], b1 = bp[4];
                mma_tf32(c[0][nt], a[0][0], a[0][1], a[0][2], a[0][3], b0, b1);
                mma_tf32(c[1][nt], a[1][0], a[1][1], a[1][2], a[1][3], b0, b1);
            }
        }
    }

    // epilogue
#pragma unroll
    for (int mt = 0; mt < 2; mt++) {
        int row0 = m0 + wm + mt * 16 + g;
        int row1 = row0 + 8;
#pragma unroll
        for (int nt = 0; nt < 4; nt++) {
            int col = n0 + wn + nt * 8 + 2 * tg;
            float b0 = bias[col], b1 = bias[col + 1];
            float v00 = c[mt][nt][0] + b0, v01 = c[mt][nt][1] + b1;
            float v10 = c[mt][nt][2] + b0, v11 = c[mt][nt][3] + b1;
            if (mode == 1) {
                v00 = fmaxf(v00, 0.f); v01 = fmaxf(v01, 0.f);
                v10 = fmaxf(v10, 0.f); v11 = fmaxf(v11, 0.f);
            }
            if (mode == 2) {
                unsigned* C = (unsigned*)Cout;
                C[((size_t)row0 * Nn + col) >> 1] = packbf(v00 * outscale, v01 * outscale);
                C[((size_t)row1 * Nn + col) >> 1] = packbf(v10 * outscale, v11 * outscale);
            } else {
                float* C = (float*)Cout;
                *reinterpret_cast<float2*>(C + (size_t)row0 * Nn + col) = make_float2(v00, v01);
                *reinterpret_cast<float2*>(C + (size_t)row1 * Nn + col) = make_float2(v10, v11);
            }
        }
    }
}

// ---------------- V transpose fp32 -> bf16 [d][n] --------------------------
__global__ void vtrans_kernel(const float* __restrict__ v,
                              __nv_bfloat16* __restrict__ vt) {
    __shared__ float tile[64][33];
    const int n0 = blockIdx.x * 64;
    const int d0 = blockIdx.y * 32;
    const int t = threadIdx.x;

    for (int i = t; i < 512; i += 256) {
        int row = i >> 3, c = i & 7;
        float4 val = *reinterpret_cast<const float4*>(v + (size_t)(n0 + row) * DD + d0 + c * 4);
        tile[row][c * 4 + 0] = val.x;
        tile[row][c * 4 + 1] = val.y;
        tile[row][c * 4 + 2] = val.z;
        tile[row][c * 4 + 3] = val.w;
    }
    __syncthreads();

    unsigned* vt32 = reinterpret_cast<unsigned*>(vt);
    for (int o = t; o < 1024; o += 256) {
        int d = o >> 5, np = o & 31;
        unsigned pk = packbf(tile[np * 2][d], tile[np * 2 + 1][d]);
        vt32[(size_t)(d0 + d) * (NN / 2) + (n0 >> 1) + np] = pk;
    }
}

// ---------------- adjacency -> bitmask (with self loop) --------------------
__global__ void maskpack_kernel(const int* __restrict__ adj,
                                unsigned* __restrict__ mbits) {
    const int r = blockIdx.x;
    const int t = threadIdx.x;   // word index 0..127
    const int4* ap = reinterpret_cast<const int4*>(adj + (size_t)r * NN + t * 32);
    unsigned m = 0;
#pragma unroll
    for (int j = 0; j < 8; j++) {
        int4 a = ap[j];
        m |= (unsigned)(a.x != 0) << (j * 4 + 0);
        m |= (unsigned)(a.y != 0) << (j * 4 + 1);
        m |= (unsigned)(a.z != 0) << (j * 4 + 2);
        m |= (unsigned)(a.w != 0) << (j * 4 + 3);
    }
    if ((r >> 5) == t) m |= 1u << (r & 31);
    mbits[(size_t)r * (NN / 32) + t] = m;
}

// ---------------- bf16 tensor-core masked attention ------------------------
// grid (NN/64, HH, KSPLIT), 128 threads = 4 warps; warp owns 16 q rows.
__global__ __launch_bounds__(128) void attn_mma_kernel(
    const __nv_bfloat16* __restrict__ qb,
    const __nv_bfloat16* __restrict__ kb,
    const __nv_bfloat16* __restrict__ vt,
    const unsigned* __restrict__ mbits,
    float* __restrict__ pacc, float* __restrict__ pl) {

    const int h = blockIdx.y, split = blockIdx.z;
    const int tid = threadIdx.x;
    const int w = tid >> 5, lane = tid & 31;
    const int g = lane >> 2, tg = lane & 3;
    const int r0 = blockIdx.x * 64;
    const int wr = r0 + w * 16;

    __shared__ alignas(16) __nv_bfloat16 Ks[64 * KSTRIDE];
    __shared__ alignas(16) __nv_bfloat16 Vs[32 * VTSTRIDE];
    __shared__ alignas(16) unsigned Ms[64][2];

    // Q A-fragments: 2 ksteps (d 0..15, 16..31) x 4 regs
    unsigned qa[2][4];
#pragma unroll
    for (int kk = 0; kk < 2; kk++) {
        const __nv_bfloat16* q0 = qb + (size_t)(wr + g) * DD + h * HDIM + kk * 16 + 2 * tg;
        const __nv_bfloat16* q1 = qb + (size_t)(wr + g + 8) * DD + h * HDIM + kk * 16 + 2 * tg;
        qa[kk][0] = *reinterpret_cast<const unsigned*>(q0);
        qa[kk][1] = *reinterpret_cast<const unsigned*>(q1);
        qa[kk][2] = *reinterpret_cast<const unsigned*>(q0 + 8);
        qa[kk][3] = *reinterpret_cast<const unsigned*>(q1 + 8);
    }

    float oc[4][4];
#pragma unroll
    for (int i = 0; i < 4; i++)
#pragma unroll
        for (int j = 0; j < 4; j++) oc[i][j] = 0.f;
    float l0 = 0.f, l1 = 0.f;

    const int kbase = split * KCHUNK;
    for (int c0 = kbase; c0 < kbase + KCHUNK; c0 += 64) {
        __syncthreads();
        // K tile: 64 keys x 32 d (bf16)
        for (int i = tid; i < 256; i += 128) {
            int row = i >> 2, c = i & 3;
            float4 val = *reinterpret_cast<const float4*>(
                kb + (size_t)(c0 + row) * DD + h * HDIM + c * 8);
            *reinterpret_cast<float4*>(Ks + row * KSTRIDE + c * 8) = val;
        }
        // V^T tile: 32 d x 64 keys
        for (int i = tid; i < 256; i += 128) {
            int row = i >> 3, c = i & 7;
            float4 val = *reinterpret_cast<const float4*>(
                vt + (size_t)(h * HDIM + row) * NN + c0 + c * 8);
            *reinterpret_cast<float4*>(Vs + row * VTSTRIDE + c * 8) = val;
        }
        // mask words: 64 rows x 2 words
        {
            int row = tid >> 1, ws = tid & 1;
            Ms[row][ws] = mbits[(size_t)(r0 + row) * (NN / 32) + (c0 >> 5) + ws];
        }
        __syncthreads();

        // ---- S = Q K^T  (16 rows x 64 keys per warp) ----
        float s[8][4];
#pragma unroll
        for (int nt = 0; nt < 8; nt++)
#pragma unroll
            for (int j = 0; j < 4; j++) s[nt][j] = 0.f;
#pragma unroll
        for (int kk = 0; kk < 2; kk++)
#pragma unroll
            for (int nt = 0; nt < 8; nt++) {
                unsigned b0 = *reinterpret_cast<const unsigned*>(
                    Ks + (nt * 8 + g) * KSTRIDE + kk * 16 + 2 * tg);
                unsigned b1 = *reinterpret_cast<const unsigned*>(
                    Ks + (nt * 8 + g) * KSTRIDE + kk * 16 + 2 * tg + 8);
                mma_bf16(s[nt], qa[kk][0], qa[kk][1], qa[kk][2], qa[kk][3], b0, b1);
            }

        // ---- mask + exp2 (scale already folded into kb) ----
        unsigned m0lo = Ms[w * 16 + g][0],     m0hi = Ms[w * 16 + g][1];
        unsigned m1lo = Ms[w * 16 + g + 8][0], m1hi = Ms[w * 16 + g + 8][1];
#pragma unroll
        for (int nt = 0; nt < 8; nt++) {
            unsigned w0 = (nt < 4) ? m0lo : m0hi;
            unsigned w1 = (nt < 4) ? m1lo : m1hi;
            int sh = (nt & 3) * 8 + 2 * tg;
            float p0 = ex2(((w0 >> sh) & 1u)       ? s[nt][0] : -64.f);
            float p1 = ex2(((w0 >> (sh + 1)) & 1u) ? s[nt][1] : -64.f);
            float p2 = ex2(((w1 >> sh) & 1u)       ? s[nt][2] : -64.f);
            float p3 = ex2(((w1 >> (sh + 1)) & 1u) ? s[nt][3] : -64.f);
            l0 += p0 + p1;
            l1 += p2 + p3;
            s[nt][0] = p0; s[nt][1] = p1; s[nt][2] = p2; s[nt][3] = p3;
        }

        // ---- O += P V  (P fragments pack directly from accumulators) ----
#pragma unroll
        for (int kk = 0; kk < 4; kk++) {
            unsigned pa0 = packbf(s[2 * kk][0],     s[2 * kk][1]);
            unsigned pa1 = packbf(s[2 * kk][2],     s[2 * kk][3]);
            unsigned pa2 = packbf(s[2 * kk + 1][0], s[2 * kk + 1][1]);
            unsigned pa3 = packbf(s[2 * kk + 1][2], s[2 * kk + 1][3]);
#pragma unroll
            for (int nd = 0; nd < 4; nd++) {
                unsigned b0 = *reinterpret_cast<const unsigned*>(
                    Vs + (nd * 8 + g) * VTSTRIDE + kk * 16 + 2 * tg);
                unsigned b1 = *reinterpret_cast<const unsigned*>(
                    Vs + (nd * 8 + g) * VTSTRIDE + kk * 16 + 2 * tg + 8);
                mma_bf16(oc[nd], pa0, pa1, pa2, pa3, b0, b1);
            }
        }
    }

    // reduce l across the 4-lane quad (same row)
    l0 += __shfl_xor_sync(0xffffffffu, l0, 1);
    l0 += __shfl_xor_sync(0xffffffffu, l0, 2);
    l1 += __shfl_xor_sync(0xffffffffu, l1, 1);
    l1 += __shfl_xor_sync(0xffffffffu, l1, 2);

    // write UNNORMALIZED numerators; the reduce kernel does the single division
    float* p0 = pacc + ((size_t)split * NN + wr + g) * DD + h * HDIM;
    float* p1 = pacc + ((size_t)split * NN + wr + g + 8) * DD + h * HDIM;
#pragma unroll
    for (int nd = 0; nd < 4; nd++) {
        int col = nd * 8 + 2 * tg;
        *reinterpret_cast<float2*>(p0 + col) = make_float2(oc[nd][0], oc[nd][1]);
        *reinterpret_cast<float2*>(p1 + col) = make_float2(oc[nd][2], oc[nd][3]);
    }
    if (tg == 0) {
        pl[((size_t)split * NN + wr + g) * HH + h] = l0;
        pl[((size_t)split * NN + wr + g + 8) * HH + h] = l1;
    }
}

// ---------------- split-K reduce ------------------------------------------
__global__ void attn_reduce_kernel(const float* __restrict__ pacc,
                                   const float* __restrict__ pl,
                                   float* __restrict__ o) {
    const int r = blockIdx.x;
    const int t = threadIdx.x;
    const int h = t >> 5;
    float s = 0.f;
#pragma unroll
    for (int sp = 0; sp < KSPLIT; sp++)
        s += pacc[((size_t)sp * NN + r) * DD + t];
    float L = 0.f;
#pragma unroll
    for (int sp = 0; sp < KSPLIT; sp++)
        L += pl[((size_t)sp * NN + r) * HH + h];
    o[(size_t)r * DD + t] = s / L;
}

// ---------------- residual add + layernorm -------------------------------
__global__ void ln_kernel(const float* __restrict__ a,
                          const float* __restrict__ res,
                          const float* __restrict__ g,
                          const float* __restrict__ beta,
                          float* __restrict__ out) {
    const int row = blockIdx.x;
    const int t = threadIdx.x;
    const int lane = t & 31, warp = t >> 5;

    float x = a[(size_t)row * DD + t] + res[(size_t)row * DD + t];
    float s = x, s2 = x * x;
#pragma unroll
    for (int off = 16; off; off >>= 1) {
        s  += __shfl_xor_sync(0xffffffffu, s, off);
        s2 += __shfl_xor_sync(0xffffffffu, s2, off);
    }
    __shared__ float sh[2][8];
    if (lane == 0) { sh[0][warp] = s; sh[1][warp] = s2; }
    __syncthreads();
    float S = 0.f, S2 = 0.f;
#pragma unroll
    for (int i = 0; i < 8; i++) { S += sh[0][i]; S2 += sh[1][i]; }

    float mu = S * (1.0f / DD);
    float var = S2 * (1.0f / DD) - mu * mu;
    float r = rsqrtf(var + EPS);
    out[(size_t)row * DD + t] = (x - mu) * r * g[t] + beta[t];
}

// ---------------- launch --------------------------------------------------
extern "C" void kernel_launch(void* const* d_in, const int* in_sizes, int n_in,
                              void* d_out, int out_size) {
    const float* x    = (const float*)d_in[0];
    const int*   adj  = (const int*)d_in[1];
    const float* Wq   = (const float*)d_in[2];
    const float* Wk   = (const float*)d_in[3];
    const float* Wv   = (const float*)d_in[4];
    const float* bq   = (const float*)d_in[5];
    const float* bk   = (const float*)d_in[6];
    const float* bv   = (const float*)d_in[7];
    const float* Wo   = (const float*)d_in[8];
    const float* bo   = (const float*)d_in[9];
    const float* g1   = (const float*)d_in[10];
    const float* be1  = (const float*)d_in[11];
    const float* W1   = (const float*)d_in[12];
    const float* b1   = (const float*)d_in[13];
    const float* W2   = (const float*)d_in[14];
    const float* b2   = (const float*)d_in[15];
    const float* g2   = (const float*)d_in[16];
    const float* be2  = (const float*)d_in[17];
    float* out = (float*)d_out;

    float *v, *o, *h, *x1, *f1, *f2, *pacc, *pl;
    __nv_bfloat16 *qb, *kb, *vt;
    unsigned *mbits;
    cudaGetSymbolAddress((void**)&v,     g_v);
    cudaGetSymbolAddress((void**)&qb,    g_qb);
    cudaGetSymbolAddress((void**)&kb,    g_kb);
    cudaGetSymbolAddress((void**)&vt,    g_vt);
    cudaGetSymbolAddress((void**)&mbits, g_mbits);
    cudaGetSymbolAddress((void**)&o,     g_o);
    cudaGetSymbolAddress((void**)&h,     g_h);
    cudaGetSymbolAddress((void**)&x1,    g_x1);
    cudaGetSymbolAddress((void**)&f1,    g_f1);
    cudaGetSymbolAddress((void**)&f2,    g_f2);
    cudaGetSymbolAddress((void**)&pacc,  g_pacc);
    cudaGetSymbolAddress((void**)&pl,    g_pl);

    const float scl = 0.17677669529663687f * 1.4426950408889634f; // 1/sqrt(32)*log2(e)

    dim3 tg(128);
    dim3 gD(DD / 64, NN / 64);        // 4 x 64
    dim3 gF1(2 * DD / 64, NN / 64);   // 8 x 64

    // mask pack (independent of projections)
    maskpack_kernel<<<NN, NN / 32>>>(adj, mbits);

    // QKV projections on tensor cores (q,k -> bf16; k pre-scaled; v -> fp32)
    gemm_tf32_kernel<<<gD, tg>>>(x, Wq, bq, qb, NN, DD, DD, 2, 1.0f);
    gemm_tf32_kernel<<<gD, tg>>>(x, Wk, bk, kb, NN, DD, DD, 2, scl);
    gemm_tf32_kernel<<<gD, tg>>>(x, Wv, bv, v,  NN, DD, DD, 0, 1.0f);
    vtrans_kernel<<<dim3(NN / 64, DD / 32), 256>>>(v, vt);

    // tensor-core masked attention (split-K) + reduce
    attn_mma_kernel<<<dim3(NN / 64, HH, KSPLIT), 128>>>(qb, kb, vt, mbits, pacc, pl);
    attn_reduce_kernel<<<NN, DD>>>(pacc, pl, o);

    // output projection + LN1
    gemm_tf32_kernel<<<gD, tg>>>(o, Wo, bo, h, NN, DD, DD, 0, 1.0f);
    ln_kernel<<<NN, DD>>>(h, x, g1, be1, x1);

    // FFN
    gemm_tf32_kernel<<<gF1, tg>>>(x1, W1, b1, f1, NN, 2 * DD, DD, 1, 1.0f);
    gemm_tf32_kernel<<<gD, tg>>>(f1, W2, b2, f2, NN, DD, 2 * DD, 0, 1.0f);

    // LN2 -> final output
    ln_kernel<<<NN, DD>>>(f2, x1, g2, be2, out);
}

// round 13
// speedup vs baseline: 6.0561x; 1.3259x over previous
#include <cuda_runtime.h>
#include <cuda_bf16.h>
#include <math.h>

#define NN 4096
#define DD 256
#define HH 8
#define HDIM 32
#define EPS 1e-5f
#define KSPLIT 2
#define KCHUNK (NN / KSPLIT)    // 2048
#define KSTRIDE 40              // attn Ks smem row stride (bf16): 80B = 5*16
#define VTSTRIDE 72             // attn Vs smem row stride (bf16): 144B = 9*16
#define GSTRIDE 36              // gemm smem row stride (words): 4g+tg conflict-free

// ---------------- scratch (device globals: allocation-free) ----------------
__device__ float          g_v[NN * DD];
__device__ __nv_bfloat16  g_qb[NN * DD];
__device__ __nv_bfloat16  g_kb[NN * DD];       // pre-scaled by scale*log2(e)
__device__ __nv_bfloat16  g_vt[DD * NN];       // V transposed: [d][n]
__device__ unsigned       g_mbits[NN * (NN / 32)];
__device__ float          g_o[NN * DD];
__device__ float          g_h[NN * DD];
__device__ float          g_x1[NN * DD];
__device__ float          g_f1[NN * 2 * DD];
__device__ float          g_f2[NN * DD];
__device__ float          g_pacc[KSPLIT * NN * DD];
__device__ float          g_pl[KSPLIT * NN * HH];

// ---------------- small PTX helpers ---------------------------------------
__device__ __forceinline__ float ex2(float x) {
    float r;
    asm("ex2.approx.ftz.f32 %0, %1;" : "=f"(r) : "f"(x));
    return r;
}
__device__ __forceinline__ unsigned packbf(float lo, float hi) {
    unsigned r;
    asm("cvt.rn.bf16x2.f32 %0, %1, %2;" : "=r"(r) : "f"(hi), "f"(lo));
    return r;
}
__device__ __forceinline__ void mma_bf16(float c[4], unsigned a0, unsigned a1,
                                         unsigned a2, unsigned a3,
                                         unsigned b0, unsigned b1) {
    asm("mma.sync.aligned.m16n8k16.row.col.f32.bf16.bf16.f32 "
        "{%0,%1,%2,%3},{%4,%5,%6,%7},{%8,%9},{%0,%1,%2,%3};"
        : "+f"(c[0]), "+f"(c[1]), "+f"(c[2]), "+f"(c[3])
        : "r"(a0), "r"(a1), "r"(a2), "r"(a3), "r"(b0), "r"(b1));
}
__device__ __forceinline__ void mma_tf32(float c[4], unsigned a0, unsigned a1,
                                         unsigned a2, unsigned a3,
                                         unsigned b0, unsigned b1) {
    asm("mma.sync.aligned.m16n8k8.row.col.f32.tf32.tf32.f32 "
        "{%0,%1,%2,%3},{%4,%5,%6,%7},{%8,%9},{%0,%1,%2,%3};"
        : "+f"(c[0]), "+f"(c[1]), "+f"(c[2]), "+f"(c[3])
        : "r"(a0), "r"(a1), "r"(a2), "r"(a3), "r"(b0), "r"(b1));
}
__device__ __forceinline__ void cpasync16(unsigned saddr, const void* gptr) {
    asm volatile("cp.async.cg.shared.global [%0], [%1], 16;" :: "r"(saddr), "l"(gptr));
}
__device__ __forceinline__ void cpcommit() {
    asm volatile("cp.async.commit_group;");
}
template <int N>
__device__ __forceinline__ void cpwait() {
    asm volatile("cp.async.wait_group %0;" :: "n"(N));
}

// ============ pipelined tf32 GEMM core (BM=64, BN=64, BK=32, 128 thr) ======
// A: [M,K] row-major, rows m0..m0+63 ; B: [Nn,K] row-major, rows n0..n0+63
// fp32 fed raw into tf32 MMA (hardware truncation, CUTLASS-style).
struct GemmAcc { float c[2][4][4]; };

__device__ __forceinline__ void gemm_core(
    const float* __restrict__ A, const float* __restrict__ B,
    int m0, int n0, int K,
    float* As, float* Bs, GemmAcc& acc) {

    const int tid = threadIdx.x;
    const int w = tid >> 5, lane = tid & 31;
    const int g = lane >> 2, tg = lane & 3;
    const int wm = (w >> 1) * 32;
    const int wn = (w & 1) * 32;

#pragma unroll
    for (int mt = 0; mt < 2; mt++)
#pragma unroll
        for (int nt = 0; nt < 4; nt++)
#pragma unroll
            for (int j = 0; j < 4; j++) acc.c[mt][nt][j] = 0.f;

    // per-thread load mapping: 4 float4 per matrix per stage
    // id = i*128+tid ; row = id>>3 (0..63), c4 = id&7 (8 float4 per 32-col row)
    unsigned sA = (unsigned)__cvta_generic_to_shared(As);
    unsigned sB = (unsigned)__cvta_generic_to_shared(Bs);
    const int stageW = 64 * GSTRIDE;           // words per stage per matrix

    const int NIT = K >> 5;                    // BK=32 steps

    // prefetch stage 0
    {
        int k0 = 0;
#pragma unroll
        for (int i = 0; i < 4; i++) {
            int id = i * 128 + tid;
            int row = id >> 3, c4 = id & 7;
            cpasync16(sA + (row * GSTRIDE + c4 * 4) * 4,
                      A + (size_t)(m0 + row) * K + k0 + c4 * 4);
            cpasync16(sB + (row * GSTRIDE + c4 * 4) * 4,
                      B + (size_t)(n0 + row) * K + k0 + c4 * 4);
        }
        cpcommit();
    }

    for (int it = 0; it < NIT; it++) {
        int cur = it & 1;
        if (it + 1 < NIT) {
            int nxt = (it + 1) & 1;
            int k0 = (it + 1) << 5;
#pragma unroll
            for (int i = 0; i < 4; i++) {
                int id = i * 128 + tid;
                int row = id >> 3, c4 = id & 7;
                cpasync16(sA + (nxt * stageW + row * GSTRIDE + c4 * 4) * 4,
                          A + (size_t)(m0 + row) * K + k0 + c4 * 4);
                cpasync16(sB + (nxt * stageW + row * GSTRIDE + c4 * 4) * 4,
                          B + (size_t)(n0 + row) * K + k0 + c4 * 4);
            }
            cpcommit();
            cpwait<1>();
        } else {
            cpwait<0>();
        }
        __syncthreads();

        const unsigned* Asu = reinterpret_cast<const unsigned*>(As) + cur * stageW;
        const unsigned* Bsu = reinterpret_cast<const unsigned*>(Bs) + cur * stageW;
#pragma unroll
        for (int kk = 0; kk < 4; kk++) {
            const int kb = kk * 8;
            unsigned a[2][4];
#pragma unroll
            for (int mt = 0; mt < 2; mt++) {
                const unsigned* ap0 = Asu + (wm + mt * 16 + g) * GSTRIDE + kb + tg;
                const unsigned* ap1 = Asu + (wm + mt * 16 + g + 8) * GSTRIDE + kb + tg;
                a[mt][0] = ap0[0];
                a[mt][1] = ap1[0];
                a[mt][2] = ap0[4];
                a[mt][3] = ap1[4];
            }
#pragma unroll
            for (int nt = 0; nt < 4; nt++) {
                const unsigned* bp = Bsu + (wn + nt * 8 + g) * GSTRIDE + kb + tg;
                unsigned b0 = bp[0], b1 = bp[4];
                mma_tf32(acc.c[0][nt], a[0][0], a[0][1], a[0][2], a[0][3], b0, b1);
                mma_tf32(acc.c[1][nt], a[1][0], a[1][1], a[1][2], a[1][3], b0, b1);
            }
        }
        __syncthreads();
    }
}

// epilogue helper: writes the warp's 32x32 tile
__device__ __forceinline__ void gemm_epilogue(
    GemmAcc& acc, const float* __restrict__ bias, void* Cout,
    int m0, int n0, int Nn, int mode, float outscale) {
    const int tid = threadIdx.x;
    const int w = tid >> 5, lane = tid & 31;
    const int g = lane >> 2, tg = lane & 3;
    const int wm = (w >> 1) * 32;
    const int wn = (w & 1) * 32;

#pragma unroll
    for (int mt = 0; mt < 2; mt++) {
        int row0 = m0 + wm + mt * 16 + g;
        int row1 = row0 + 8;
#pragma unroll
        for (int nt = 0; nt < 4; nt++) {
            int col = n0 + wn + nt * 8 + 2 * tg;
            float b0 = bias[col], b1 = bias[col + 1];
            float v00 = acc.c[mt][nt][0] + b0, v01 = acc.c[mt][nt][1] + b1;
            float v10 = acc.c[mt][nt][2] + b0, v11 = acc.c[mt][nt][3] + b1;
            if (mode == 1) {
                v00 = fmaxf(v00, 0.f); v01 = fmaxf(v01, 0.f);
                v10 = fmaxf(v10, 0.f); v11 = fmaxf(v11, 0.f);
            }
            if (mode == 2) {
                unsigned* C = (unsigned*)Cout;
                C[((size_t)row0 * Nn + col) >> 1] = packbf(v00 * outscale, v01 * outscale);
                C[((size_t)row1 * Nn + col) >> 1] = packbf(v10 * outscale, v11 * outscale);
            } else {
                float* C = (float*)Cout;
                *reinterpret_cast<float2*>(C + (size_t)row0 * Nn + col) = make_float2(v00, v01);
                *reinterpret_cast<float2*>(C + (size_t)row1 * Nn + col) = make_float2(v10, v11);
            }
        }
    }
}

// ---------------- generic pipelined GEMM kernel ----------------------------
__global__ __launch_bounds__(128) void gemm_tf32_kernel(
    const float* __restrict__ A, const float* __restrict__ B,
    const float* __restrict__ bias, void* __restrict__ Cout,
    int M, int Nn, int K, int mode, float outscale) {
    __shared__ alignas(16) float As[2 * 64 * GSTRIDE];
    __shared__ alignas(16) float Bs[2 * 64 * GSTRIDE];
    GemmAcc acc;
    int m0 = blockIdx.y * 64, n0 = blockIdx.x * 64;
    gemm_core(A, B, m0, n0, K, As, Bs, acc);
    gemm_epilogue(acc, bias, Cout, m0, n0, Nn, mode, outscale);
}

// ---------------- fused QKV kernel: one wide launch ------------------------
// grid.x = 12: segments [0..3]=Q, [4..7]=K, [8..11]=V
__global__ __launch_bounds__(128) void qkv_tf32_kernel(
    const float* __restrict__ x,
    const float* __restrict__ Wq, const float* __restrict__ Wk, const float* __restrict__ Wv,
    const float* __restrict__ bq, const float* __restrict__ bk, const float* __restrict__ bv,
    __nv_bfloat16* __restrict__ qb, __nv_bfloat16* __restrict__ kb, float* __restrict__ v,
    float scl) {
    __shared__ alignas(16) float As[2 * 64 * GSTRIDE];
    __shared__ alignas(16) float Bs[2 * 64 * GSTRIDE];
    GemmAcc acc;
    int seg = blockIdx.x >> 2;
    int n0 = (blockIdx.x & 3) * 64;
    int m0 = blockIdx.y * 64;
    const float* B    = (seg == 0) ? Wq : (seg == 1) ? Wk : Wv;
    const float* bias = (seg == 0) ? bq : (seg == 1) ? bk : bv;
    gemm_core(x, B, m0, n0, DD, As, Bs, acc);
    if (seg == 0)      gemm_epilogue(acc, bias, qb, m0, n0, DD, 2, 1.0f);
    else if (seg == 1) gemm_epilogue(acc, bias, kb, m0, n0, DD, 2, scl);
    else               gemm_epilogue(acc, bias, v,  m0, n0, DD, 0, 1.0f);
}

// ---------------- V transpose fp32 -> bf16 [d][n] --------------------------
__global__ void vtrans_kernel(const float* __restrict__ v,
                              __nv_bfloat16* __restrict__ vt) {
    __shared__ float tile[64][33];
    const int n0 = blockIdx.x * 64;
    const int d0 = blockIdx.y * 32;
    const int t = threadIdx.x;

    for (int i = t; i < 512; i += 256) {
        int row = i >> 3, c = i & 7;
        float4 val = *reinterpret_cast<const float4*>(v + (size_t)(n0 + row) * DD + d0 + c * 4);
        tile[row][c * 4 + 0] = val.x;
        tile[row][c * 4 + 1] = val.y;
        tile[row][c * 4 + 2] = val.z;
        tile[row][c * 4 + 3] = val.w;
    }
    __syncthreads();

    unsigned* vt32 = reinterpret_cast<unsigned*>(vt);
    for (int o = t; o < 1024; o += 256) {
        int d = o >> 5, np = o & 31;
        unsigned pk = packbf(tile[np * 2][d], tile[np * 2 + 1][d]);
        vt32[(size_t)(d0 + d) * (NN / 2) + (n0 >> 1) + np] = pk;
    }
}

// ---------------- adjacency -> bitmask (with self loop) --------------------
__global__ void maskpack_kernel(const int* __restrict__ adj,
                                unsigned* __restrict__ mbits) {
    const int r = blockIdx.x;
    const int t = threadIdx.x;   // word index 0..127
    const int4* ap = reinterpret_cast<const int4*>(adj + (size_t)r * NN + t * 32);
    unsigned m = 0;
#pragma unroll
    for (int j = 0; j < 8; j++) {
        int4 a = ap[j];
        m |= (unsigned)(a.x != 0) << (j * 4 + 0);
        m |= (unsigned)(a.y != 0) << (j * 4 + 1);
        m |= (unsigned)(a.z != 0) << (j * 4 + 2);
        m |= (unsigned)(a.w != 0) << (j * 4 + 3);
    }
    if ((r >> 5) == t) m |= 1u << (r & 31);
    mbits[(size_t)r * (NN / 32) + t] = m;
}

// ---------------- bf16 tensor-core masked attention ------------------------
__global__ __launch_bounds__(128) void attn_mma_kernel(
    const __nv_bfloat16* __restrict__ qb,
    const __nv_bfloat16* __restrict__ kb,
    const __nv_bfloat16* __restrict__ vt,
    const unsigned* __restrict__ mbits,
    float* __restrict__ pacc, float* __restrict__ pl) {

    const int h = blockIdx.y, split = blockIdx.z;
    const int tid = threadIdx.x;
    const int w = tid >> 5, lane = tid & 31;
    const int g = lane >> 2, tg = lane & 3;
    const int r0 = blockIdx.x * 64;
    const int wr = r0 + w * 16;

    __shared__ alignas(16) __nv_bfloat16 Ks[64 * KSTRIDE];
    __shared__ alignas(16) __nv_bfloat16 Vs[32 * VTSTRIDE];
    __shared__ alignas(16) unsigned Ms[64][2];

    unsigned qa[2][4];
#pragma unroll
    for (int kk = 0; kk < 2; kk++) {
        const __nv_bfloat16* q0 = qb + (size_t)(wr + g) * DD + h * HDIM + kk * 16 + 2 * tg;
        const __nv_bfloat16* q1 = qb + (size_t)(wr + g + 8) * DD + h * HDIM + kk * 16 + 2 * tg;
        qa[kk][0] = *reinterpret_cast<const unsigned*>(q0);
        qa[kk][1] = *reinterpret_cast<const unsigned*>(q1);
        qa[kk][2] = *reinterpret_cast<const unsigned*>(q0 + 8);
        qa[kk][3] = *reinterpret_cast<const unsigned*>(q1 + 8);
    }

    float oc[4][4];
#pragma unroll
    for (int i = 0; i < 4; i++)
#pragma unroll
        for (int j = 0; j < 4; j++) oc[i][j] = 0.f;
    float l0 = 0.f, l1 = 0.f;

    const int kbase = split * KCHUNK;
    for (int c0 = kbase; c0 < kbase + KCHUNK; c0 += 64) {
        __syncthreads();
        for (int i = tid; i < 256; i += 128) {
            int row = i >> 2, c = i & 3;
            float4 val = *reinterpret_cast<const float4*>(
                kb + (size_t)(c0 + row) * DD + h * HDIM + c * 8);
            *reinterpret_cast<float4*>(Ks + row * KSTRIDE + c * 8) = val;
        }
        for (int i = tid; i < 256; i += 128) {
            int row = i >> 3, c = i & 7;
            float4 val = *reinterpret_cast<const float4*>(
                vt + (size_t)(h * HDIM + row) * NN + c0 + c * 8);
            *reinterpret_cast<float4*>(Vs + row * VTSTRIDE + c * 8) = val;
        }
        {
            int row = tid >> 1, ws = tid & 1;
            Ms[row][ws] = mbits[(size_t)(r0 + row) * (NN / 32) + (c0 >> 5) + ws];
        }
        __syncthreads();

        float s[8][4];
#pragma unroll
        for (int nt = 0; nt < 8; nt++)
#pragma unroll
            for (int j = 0; j < 4; j++) s[nt][j] = 0.f;
#pragma unroll
        for (int kk = 0; kk < 2; kk++)
#pragma unroll
            for (int nt = 0; nt < 8; nt++) {
                unsigned b0 = *reinterpret_cast<const unsigned*>(
                    Ks + (nt * 8 + g) * KSTRIDE + kk * 16 + 2 * tg);
                unsigned b1 = *reinterpret_cast<const unsigned*>(
                    Ks + (nt * 8 + g) * KSTRIDE + kk * 16 + 2 * tg + 8);
                mma_bf16(s[nt], qa[kk][0], qa[kk][1], qa[kk][2], qa[kk][3], b0, b1);
            }

        unsigned m0lo = Ms[w * 16 + g][0],     m0hi = Ms[w * 16 + g][1];
        unsigned m1lo = Ms[w * 16 + g + 8][0], m1hi = Ms[w * 16 + g + 8][1];
#pragma unroll
        for (int nt = 0; nt < 8; nt++) {
            unsigned w0 = (nt < 4) ? m0lo : m0hi;
            unsigned w1 = (nt < 4) ? m1lo : m1hi;
            int sh = (nt & 3) * 8 + 2 * tg;
            float p0 = ex2(((w0 >> sh) & 1u)       ? s[nt][0] : -64.f);
            float p1 = ex2(((w0 >> (sh + 1)) & 1u) ? s[nt][1] : -64.f);
            float p2 = ex2(((w1 >> sh) & 1u)       ? s[nt][2] : -64.f);
            float p3 = ex2(((w1 >> (sh + 1)) & 1u) ? s[nt][3] : -64.f);
            l0 += p0 + p1;
            l1 += p2 + p3;
            s[nt][0] = p0; s[nt][1] = p1; s[nt][2] = p2; s[nt][3] = p3;
        }

#pragma unroll
        for (int kk = 0; kk < 4; kk++) {
            unsigned pa0 = packbf(s[2 * kk][0],     s[2 * kk][1]);
            unsigned pa1 = packbf(s[2 * kk][2],     s[2 * kk][3]);
            unsigned pa2 = packbf(s[2 * kk + 1][0], s[2 * kk + 1][1]);
            unsigned pa3 = packbf(s[2 * kk + 1][2], s[2 * kk + 1][3]);
#pragma unroll
            for (int nd = 0; nd < 4; nd++) {
                unsigned b0 = *reinterpret_cast<const unsigned*>(
                    Vs + (nd * 8 + g) * VTSTRIDE + kk * 16 + 2 * tg);
                unsigned b1 = *reinterpret_cast<const unsigned*>(
                    Vs + (nd * 8 + g) * VTSTRIDE + kk * 16 + 2 * tg + 8);
                mma_bf16(oc[nd], pa0, pa1, pa2, pa3, b0, b1);
            }
        }
    }

    l0 += __shfl_xor_sync(0xffffffffu, l0, 1);
    l0 += __shfl_xor_sync(0xffffffffu, l0, 2);
    l1 += __shfl_xor_sync(0xffffffffu, l1, 1);
    l1 += __shfl_xor_sync(0xffffffffu, l1, 2);

    float* p0 = pacc + ((size_t)split * NN + wr + g) * DD + h * HDIM;
    float* p1 = pacc + ((size_t)split * NN + wr + g + 8) * DD + h * HDIM;
#pragma unroll
    for (int nd = 0; nd < 4; nd++) {
        int col = nd * 8 + 2 * tg;
        *reinterpret_cast<float2*>(p0 + col) = make_float2(oc[nd][0], oc[nd][1]);
        *reinterpret_cast<float2*>(p1 + col) = make_float2(oc[nd][2], oc[nd][3]);
    }
    if (tg == 0) {
        pl[((size_t)split * NN + wr + g) * HH + h] = l0;
        pl[((size_t)split * NN + wr + g + 8) * HH + h] = l1;
    }
}

// ---------------- split-K reduce ------------------------------------------
__global__ void attn_reduce_kernel(const float* __restrict__ pacc,
                                   const float* __restrict__ pl,
                                   float* __restrict__ o) {
    const int r = blockIdx.x;
    const int t = threadIdx.x;
    const int h = t >> 5;
    float s = 0.f;
#pragma unroll
    for (int sp = 0; sp < KSPLIT; sp++)
        s += pacc[((size_t)sp * NN + r) * DD + t];
    float L = 0.f;
#pragma unroll
    for (int sp = 0; sp < KSPLIT; sp++)
        L += pl[((size_t)sp * NN + r) * HH + h];
    o[(size_t)r * DD + t] = s / L;
}

// ---------------- residual add + layernorm -------------------------------
__global__ void ln_kernel(const float* __restrict__ a,
                          const float* __restrict__ res,
                          const float* __restrict__ g,
                          const float* __restrict__ beta,
                          float* __restrict__ out) {
    const int row = blockIdx.x;
    const int t = threadIdx.x;
    const int lane = t & 31, warp = t >> 5;

    float x = a[(size_t)row * DD + t] + res[(size_t)row * DD + t];
    float s = x, s2 = x * x;
#pragma unroll
    for (int off = 16; off; off >>= 1) {
        s  += __shfl_xor_sync(0xffffffffu, s, off);
        s2 += __shfl_xor_sync(0xffffffffu, s2, off);
    }
    __shared__ float sh[2][8];
    if (lane == 0) { sh[0][warp] = s; sh[1][warp] = s2; }
    __syncthreads();
    float S = 0.f, S2 = 0.f;
#pragma unroll
    for (int i = 0; i < 8; i++) { S += sh[0][i]; S2 += sh[1][i]; }

    float mu = S * (1.0f / DD);
    float var = S2 * (1.0f / DD) - mu * mu;
    float r = rsqrtf(var + EPS);
    out[(size_t)row * DD + t] = (x - mu) * r * g[t] + beta[t];
}

// ---------------- launch --------------------------------------------------
extern "C" void kernel_launch(void* const* d_in, const int* in_sizes, int n_in,
                              void* d_out, int out_size) {
    const float* x    = (const float*)d_in[0];
    const int*   adj  = (const int*)d_in[1];
    const float* Wq   = (const float*)d_in[2];
    const float* Wk   = (const float*)d_in[3];
    const float* Wv   = (const float*)d_in[4];
    const float* bq   = (const float*)d_in[5];
    const float* bk   = (const float*)d_in[6];
    const float* bv   = (const float*)d_in[7];
    const float* Wo   = (const float*)d_in[8];
    const float* bo   = (const float*)d_in[9];
    const float* g1   = (const float*)d_in[10];
    const float* be1  = (const float*)d_in[11];
    const float* W1   = (const float*)d_in[12];
    const float* b1   = (const float*)d_in[13];
    const float* W2   = (const float*)d_in[14];
    const float* b2   = (const float*)d_in[15];
    const float* g2   = (const float*)d_in[16];
    const float* be2  = (const float*)d_in[17];
    float* out = (float*)d_out;

    float *v, *o, *h, *x1, *f1, *f2, *pacc, *pl;
    __nv_bfloat16 *qb, *kb, *vt;
    unsigned *mbits;
    cudaGetSymbolAddress((void**)&v,     g_v);
    cudaGetSymbolAddress((void**)&qb,    g_qb);
    cudaGetSymbolAddress((void**)&kb,    g_kb);
    cudaGetSymbolAddress((void**)&vt,    g_vt);
    cudaGetSymbolAddress((void**)&mbits, g_mbits);
    cudaGetSymbolAddress((void**)&o,     g_o);
    cudaGetSymbolAddress((void**)&h,     g_h);
    cudaGetSymbolAddress((void**)&x1,    g_x1);
    cudaGetSymbolAddress((void**)&f1,    g_f1);
    cudaGetSymbolAddress((void**)&f2,    g_f2);
    cudaGetSymbolAddress((void**)&pacc,  g_pacc);
    cudaGetSymbolAddress((void**)&pl,    g_pl);

    const float scl = 0.17677669529663687f * 1.4426950408889634f; // 1/sqrt(32)*log2(e)

    dim3 tg(128);
    dim3 gD(DD / 64, NN / 64);        // 4 x 64
    dim3 gF1(2 * DD / 64, NN / 64);   // 8 x 64

    // mask pack (independent of projections)
    maskpack_kernel<<<NN, NN / 32>>>(adj, mbits);

    // fused QKV projection: one wide launch (q,k -> bf16; k pre-scaled; v -> fp32)
    qkv_tf32_kernel<<<dim3(12, NN / 64), tg>>>(x, Wq, Wk, Wv, bq, bk, bv, qb, kb, v, scl);
    vtrans_kernel<<<dim3(NN / 64, DD / 32), 256>>>(v, vt);

    // tensor-core masked attention (split-K) + reduce
    attn_mma_kernel<<<dim3(NN / 64, HH, KSPLIT), 128>>>(qb, kb, vt, mbits, pacc, pl);
    attn_reduce_kernel<<<NN, DD>>>(pacc, pl, o);

    // output projection + LN1
    gemm_tf32_kernel<<<gD, tg>>>(o, Wo, bo, h, NN, DD, DD, 0, 1.0f);
    ln_kernel<<<NN, DD>>>(h, x, g1, be1, x1);

    // FFN
    gemm_tf32_kernel<<<gF1, tg>>>(x1, W1, b1, f1, NN, 2 * DD, DD, 1, 1.0f);
    gemm_tf32_kernel<<<gD, tg>>>(f1, W2, b2, f2, NN, DD, 2 * DD, 0, 1.0f);

    // LN2 -> final output
    ln_kernel<<<NN, DD>>>(f2, x1, g2, be2, out);
}

// round 14
// speedup vs baseline: 6.0698x; 1.0023x over previous
#include <cuda_runtime.h>
#include <cuda_bf16.h>
#include <math.h>

#define NN 4096
#define DD 256
#define HH 8
#define HDIM 32
#define EPS 1e-5f
#define KSPLIT 2
#define KCHUNK (NN / KSPLIT)    // 2048
#define KSTRIDE 40              // attn Ks smem row stride (bf16): 80B = 5*16
#define VTSTRIDE 72             // attn Vs smem row stride (bf16): 144B = 9*16
#define GSTRIDE 36              // gemm smem row stride (words): 4g+tg conflict-free
#define KBYTES (64 * KSTRIDE * 2)    // 5120
#define VBYTES (32 * VTSTRIDE * 2)   // 4608

// ---------------- scratch (device globals: allocation-free) ----------------
__device__ float          g_v[NN * DD];
__device__ __nv_bfloat16  g_qb[NN * DD];
__device__ __nv_bfloat16  g_kb[NN * DD];       // pre-scaled by scale*log2(e)
__device__ __nv_bfloat16  g_vt[DD * NN];       // V transposed: [d][n]
__device__ unsigned       g_mbits[NN * (NN / 32)];
__device__ float          g_o[NN * DD];
__device__ float          g_h[NN * DD];
__device__ float          g_x1[NN * DD];
__device__ float          g_f1[NN * 2 * DD];
__device__ float          g_f2[NN * DD];
__device__ float          g_pacc[KSPLIT * NN * DD];
__device__ float          g_pl[KSPLIT * NN * HH];

// ---------------- small PTX helpers ---------------------------------------
__device__ __forceinline__ float ex2(float x) {
    float r;
    asm("ex2.approx.ftz.f32 %0, %1;" : "=f"(r) : "f"(x));
    return r;
}
__device__ __forceinline__ unsigned packbf(float lo, float hi) {
    unsigned r;
    asm("cvt.rn.bf16x2.f32 %0, %1, %2;" : "=r"(r) : "f"(hi), "f"(lo));
    return r;
}
__device__ __forceinline__ void mma_bf16(float c[4], unsigned a0, unsigned a1,
                                         unsigned a2, unsigned a3,
                                         unsigned b0, unsigned b1) {
    asm("mma.sync.aligned.m16n8k16.row.col.f32.bf16.bf16.f32 "
        "{%0,%1,%2,%3},{%4,%5,%6,%7},{%8,%9},{%0,%1,%2,%3};"
        : "+f"(c[0]), "+f"(c[1]), "+f"(c[2]), "+f"(c[3])
        : "r"(a0), "r"(a1), "r"(a2), "r"(a3), "r"(b0), "r"(b1));
}
__device__ __forceinline__ void mma_tf32(float c[4], unsigned a0, unsigned a1,
                                         unsigned a2, unsigned a3,
                                         unsigned b0, unsigned b1) {
    asm("mma.sync.aligned.m16n8k8.row.col.f32.tf32.tf32.f32 "
        "{%0,%1,%2,%3},{%4,%5,%6,%7},{%8,%9},{%0,%1,%2,%3};"
        : "+f"(c[0]), "+f"(c[1]), "+f"(c[2]), "+f"(c[3])
        : "r"(a0), "r"(a1), "r"(a2), "r"(a3), "r"(b0), "r"(b1));
}
__device__ __forceinline__ void ldsm4(unsigned& r0, unsigned& r1,
                                      unsigned& r2, unsigned& r3, unsigned addr) {
    asm volatile("ldmatrix.sync.aligned.m8n8.x4.shared.b16 {%0,%1,%2,%3}, [%4];"
        : "=r"(r0), "=r"(r1), "=r"(r2), "=r"(r3) : "r"(addr));
}
__device__ __forceinline__ void cpasync16(unsigned saddr, const void* gptr) {
    asm volatile("cp.async.cg.shared.global [%0], [%1], 16;" :: "r"(saddr), "l"(gptr));
}
__device__ __forceinline__ void cpcommit() {
    asm volatile("cp.async.commit_group;");
}
template <int N>
__device__ __forceinline__ void cpwait() {
    asm volatile("cp.async.wait_group %0;" :: "n"(N));
}

// ============ pipelined tf32 GEMM core (BM=64, BN=64, BK=32, 128 thr) ======
struct GemmAcc { float c[2][4][4]; };

__device__ __forceinline__ void gemm_core(
    const float* __restrict__ A, const float* __restrict__ B,
    int m0, int n0, int K,
    float* As, float* Bs, GemmAcc& acc) {

    const int tid = threadIdx.x;
    const int w = tid >> 5, lane = tid & 31;
    const int g = lane >> 2, tg = lane & 3;
    const int wm = (w >> 1) * 32;
    const int wn = (w & 1) * 32;

#pragma unroll
    for (int mt = 0; mt < 2; mt++)
#pragma unroll
        for (int nt = 0; nt < 4; nt++)
#pragma unroll
            for (int j = 0; j < 4; j++) acc.c[mt][nt][j] = 0.f;

    unsigned sA = (unsigned)__cvta_generic_to_shared(As);
    unsigned sB = (unsigned)__cvta_generic_to_shared(Bs);
    const int stageW = 64 * GSTRIDE;

    const int NIT = K >> 5;

    {
        int k0 = 0;
#pragma unroll
        for (int i = 0; i < 4; i++) {
            int id = i * 128 + tid;
            int row = id >> 3, c4 = id & 7;
            cpasync16(sA + (row * GSTRIDE + c4 * 4) * 4,
                      A + (size_t)(m0 + row) * K + k0 + c4 * 4);
            cpasync16(sB + (row * GSTRIDE + c4 * 4) * 4,
                      B + (size_t)(n0 + row) * K + k0 + c4 * 4);
        }
        cpcommit();
    }

    for (int it = 0; it < NIT; it++) {
        int cur = it & 1;
        if (it + 1 < NIT) {
            int nxt = (it + 1) & 1;
            int k0 = (it + 1) << 5;
#pragma unroll
            for (int i = 0; i < 4; i++) {
                int id = i * 128 + tid;
                int row = id >> 3, c4 = id & 7;
                cpasync16(sA + (nxt * stageW + row * GSTRIDE + c4 * 4) * 4,
                          A + (size_t)(m0 + row) * K + k0 + c4 * 4);
                cpasync16(sB + (nxt * stageW + row * GSTRIDE + c4 * 4) * 4,
                          B + (size_t)(n0 + row) * K + k0 + c4 * 4);
            }
            cpcommit();
            cpwait<1>();
        } else {
            cpwait<0>();
        }
        __syncthreads();

        const unsigned* Asu = reinterpret_cast<const unsigned*>(As) + cur * stageW;
        const unsigned* Bsu = reinterpret_cast<const unsigned*>(Bs) + cur * stageW;
#pragma unroll
        for (int kk = 0; kk < 4; kk++) {
            const int kb = kk * 8;
            unsigned a[2][4];
#pragma unroll
            for (int mt = 0; mt < 2; mt++) {
                const unsigned* ap0 = Asu + (wm + mt * 16 + g) * GSTRIDE + kb + tg;
                const unsigned* ap1 = Asu + (wm + mt * 16 + g + 8) * GSTRIDE + kb + tg;
                a[mt][0] = ap0[0];
                a[mt][1] = ap1[0];
                a[mt][2] = ap0[4];
                a[mt][3] = ap1[4];
            }
#pragma unroll
            for (int nt = 0; nt < 4; nt++) {
                const unsigned* bp = Bsu + (wn + nt * 8 + g) * GSTRIDE + kb + tg;
                unsigned b0 = bp[0], b1 = bp[4];
                mma_tf32(acc.c[0][nt], a[0][0], a[0][1], a[0][2], a[0][3], b0, b1);
                mma_tf32(acc.c[1][nt], a[1][0], a[1][1], a[1][2], a[1][3], b0, b1);
            }
        }
        __syncthreads();
    }
}

__device__ __forceinline__ void gemm_epilogue(
    GemmAcc& acc, const float* __restrict__ bias, void* Cout,
    int m0, int n0, int Nn, int mode, float outscale) {
    const int tid = threadIdx.x;
    const int w = tid >> 5, lane = tid & 31;
    const int g = lane >> 2, tg = lane & 3;
    const int wm = (w >> 1) * 32;
    const int wn = (w & 1) * 32;

#pragma unroll
    for (int mt = 0; mt < 2; mt++) {
        int row0 = m0 + wm + mt * 16 + g;
        int row1 = row0 + 8;
#pragma unroll
        for (int nt = 0; nt < 4; nt++) {
            int col = n0 + wn + nt * 8 + 2 * tg;
            float b0 = bias[col], b1 = bias[col + 1];
            float v00 = acc.c[mt][nt][0] + b0, v01 = acc.c[mt][nt][1] + b1;
            float v10 = acc.c[mt][nt][2] + b0, v11 = acc.c[mt][nt][3] + b1;
            if (mode == 1) {
                v00 = fmaxf(v00, 0.f); v01 = fmaxf(v01, 0.f);
                v10 = fmaxf(v10, 0.f); v11 = fmaxf(v11, 0.f);
            }
            if (mode == 2) {
                unsigned* C = (unsigned*)Cout;
                C[((size_t)row0 * Nn + col) >> 1] = packbf(v00 * outscale, v01 * outscale);
                C[((size_t)row1 * Nn + col) >> 1] = packbf(v10 * outscale, v11 * outscale);
            } else {
                float* C = (float*)Cout;
                *reinterpret_cast<float2*>(C + (size_t)row0 * Nn + col) = make_float2(v00, v01);
                *reinterpret_cast<float2*>(C + (size_t)row1 * Nn + col) = make_float2(v10, v11);
            }
        }
    }
}

__global__ __launch_bounds__(128) void gemm_tf32_kernel(
    const float* __restrict__ A, const float* __restrict__ B,
    const float* __restrict__ bias, void* __restrict__ Cout,
    int M, int Nn, int K, int mode, float outscale) {
    __shared__ alignas(16) float As[2 * 64 * GSTRIDE];
    __shared__ alignas(16) float Bs[2 * 64 * GSTRIDE];
    GemmAcc acc;
    int m0 = blockIdx.y * 64, n0 = blockIdx.x * 64;
    gemm_core(A, B, m0, n0, K, As, Bs, acc);
    gemm_epilogue(acc, bias, Cout, m0, n0, Nn, mode, outscale);
}

// ---------------- fused QKV kernel: one wide launch ------------------------
__global__ __launch_bounds__(128) void qkv_tf32_kernel(
    const float* __restrict__ x,
    const float* __restrict__ Wq, const float* __restrict__ Wk, const float* __restrict__ Wv,
    const float* __restrict__ bq, const float* __restrict__ bk, const float* __restrict__ bv,
    __nv_bfloat16* __restrict__ qb, __nv_bfloat16* __restrict__ kb, float* __restrict__ v,
    float scl) {
    __shared__ alignas(16) float As[2 * 64 * GSTRIDE];
    __shared__ alignas(16) float Bs[2 * 64 * GSTRIDE];
    GemmAcc acc;
    int seg = blockIdx.x >> 2;
    int n0 = (blockIdx.x & 3) * 64;
    int m0 = blockIdx.y * 64;
    const float* B    = (seg == 0) ? Wq : (seg == 1) ? Wk : Wv;
    const float* bias = (seg == 0) ? bq : (seg == 1) ? bk : bv;
    gemm_core(x, B, m0, n0, DD, As, Bs, acc);
    if (seg == 0)      gemm_epilogue(acc, bias, qb, m0, n0, DD, 2, 1.0f);
    else if (seg == 1) gemm_epilogue(acc, bias, kb, m0, n0, DD, 2, scl);
    else               gemm_epilogue(acc, bias, v,  m0, n0, DD, 0, 1.0f);
}

// ---------------- V transpose fp32 -> bf16 [d][n] --------------------------
__global__ void vtrans_kernel(const float* __restrict__ v,
                              __nv_bfloat16* __restrict__ vt) {
    __shared__ float tile[64][33];
    const int n0 = blockIdx.x * 64;
    const int d0 = blockIdx.y * 32;
    const int t = threadIdx.x;

    for (int i = t; i < 512; i += 256) {
        int row = i >> 3, c = i & 7;
        float4 val = *reinterpret_cast<const float4*>(v + (size_t)(n0 + row) * DD + d0 + c * 4);
        tile[row][c * 4 + 0] = val.x;
        tile[row][c * 4 + 1] = val.y;
        tile[row][c * 4 + 2] = val.z;
        tile[row][c * 4 + 3] = val.w;
    }
    __syncthreads();

    unsigned* vt32 = reinterpret_cast<unsigned*>(vt);
    for (int o = t; o < 1024; o += 256) {
        int d = o >> 5, np = o & 31;
        unsigned pk = packbf(tile[np * 2][d], tile[np * 2 + 1][d]);
        vt32[(size_t)(d0 + d) * (NN / 2) + (n0 >> 1) + np] = pk;
    }
}

// ---------------- adjacency -> bitmask (with self loop) --------------------
__global__ void maskpack_kernel(const int* __restrict__ adj,
                                unsigned* __restrict__ mbits) {
    const int r = blockIdx.x;
    const int t = threadIdx.x;
    const int4* ap = reinterpret_cast<const int4*>(adj + (size_t)r * NN + t * 32);
    unsigned m = 0;
#pragma unroll
    for (int j = 0; j < 8; j++) {
        int4 a = ap[j];
        m |= (unsigned)(a.x != 0) << (j * 4 + 0);
        m |= (unsigned)(a.y != 0) << (j * 4 + 1);
        m |= (unsigned)(a.z != 0) << (j * 4 + 2);
        m |= (unsigned)(a.w != 0) << (j * 4 + 3);
    }
    if ((r >> 5) == t) m |= 1u << (r & 31);
    mbits[(size_t)r * (NN / 32) + t] = m;
}

// ---------------- bf16 tensor-core masked attention (ldmatrix + cp.async) --
// grid (NN/64, HH, KSPLIT), 128 threads = 4 warps; warp owns 16 q rows.
__global__ __launch_bounds__(128) void attn_mma_kernel(
    const __nv_bfloat16* __restrict__ qb,
    const __nv_bfloat16* __restrict__ kb,
    const __nv_bfloat16* __restrict__ vt,
    const unsigned* __restrict__ mbits,
    float* __restrict__ pacc, float* __restrict__ pl) {

    const int h = blockIdx.y, split = blockIdx.z;
    const int tid = threadIdx.x;
    const int w = tid >> 5, lane = tid & 31;
    const int g = lane >> 2, tg = lane & 3;
    const int r0 = blockIdx.x * 64;
    const int wr = r0 + w * 16;

    __shared__ alignas(16) __nv_bfloat16 Ks[2][64 * KSTRIDE];
    __shared__ alignas(16) __nv_bfloat16 Vs[2][32 * VTSTRIDE];

    const unsigned sK = (unsigned)__cvta_generic_to_shared(&Ks[0][0]);
    const unsigned sV = (unsigned)__cvta_generic_to_shared(&Vs[0][0]);

    // Q A-fragments
    unsigned qa[2][4];
#pragma unroll
    for (int kk = 0; kk < 2; kk++) {
        const __nv_bfloat16* q0 = qb + (size_t)(wr + g) * DD + h * HDIM + kk * 16 + 2 * tg;
        const __nv_bfloat16* q1 = qb + (size_t)(wr + g + 8) * DD + h * HDIM + kk * 16 + 2 * tg;
        qa[kk][0] = *reinterpret_cast<const unsigned*>(q0);
        qa[kk][1] = *reinterpret_cast<const unsigned*>(q1);
        qa[kk][2] = *reinterpret_cast<const unsigned*>(q0 + 8);
        qa[kk][3] = *reinterpret_cast<const unsigned*>(q1 + 8);
    }

    float oc[4][4];
#pragma unroll
    for (int i = 0; i < 4; i++)
#pragma unroll
        for (int j = 0; j < 4; j++) oc[i][j] = 0.f;
    float l0 = 0.f, l1 = 0.f;

    const int kbase = split * KCHUNK;
    const int NT = KCHUNK / 64;   // 32 tiles

    // ldmatrix lane addressing (bytes within a stage)
    const int lrow = lane & 7, lk8 = lane >> 3;   // row-in-8, k-block
    // mask row pointers (L2-hot; same line across quads)
    const unsigned* mp0 = mbits + (size_t)(wr + g) * (NN / 32) + (kbase >> 5);
    const unsigned* mp1 = mbits + (size_t)(wr + g + 8) * (NN / 32) + (kbase >> 5);

    // prefetch tile 0
    {
        int c0 = kbase;
#pragma unroll
        for (int i = 0; i < 2; i++) {          // K: 64 rows x 4 chunks
            int id = i * 128 + tid;
            int row = id >> 2, c4 = id & 3;
            cpasync16(sK + (row * KSTRIDE + c4 * 8) * 2,
                      kb + (size_t)(c0 + row) * DD + h * HDIM + c4 * 8);
        }
#pragma unroll
        for (int i = 0; i < 2; i++) {          // V: 32 rows x 8 chunks
            int id = i * 128 + tid;
            int row = id >> 3, c4 = id & 7;
            cpasync16(sV + (row * VTSTRIDE + c4 * 8) * 2,
                      vt + (size_t)(h * HDIM + row) * NN + c0 + c4 * 8);
        }
        cpcommit();
    }

    for (int it = 0; it < NT; it++) {
        const int cur = it & 1;
        if (it + 1 < NT) {
            const int nxt = (it + 1) & 1;
            const int c0 = kbase + (it + 1) * 64;
#pragma unroll
            for (int i = 0; i < 2; i++) {
                int id = i * 128 + tid;
                int row = id >> 2, c4 = id & 3;
                cpasync16(sK + nxt * KBYTES + (row * KSTRIDE + c4 * 8) * 2,
                          kb + (size_t)(c0 + row) * DD + h * HDIM + c4 * 8);
            }
#pragma unroll
            for (int i = 0; i < 2; i++) {
                int id = i * 128 + tid;
                int row = id >> 3, c4 = id & 7;
                cpasync16(sV + nxt * VBYTES + (row * VTSTRIDE + c4 * 8) * 2,
                          vt + (size_t)(h * HDIM + row) * NN + c0 + c4 * 8);
            }
            cpcommit();
            cpwait<1>();
        } else {
            cpwait<0>();
        }
        __syncthreads();

        // mask words for this tile (issue early, consumed after S mma)
        unsigned m0lo = mp0[2 * it], m0hi = mp0[2 * it + 1];
        unsigned m1lo = mp1[2 * it], m1hi = mp1[2 * it + 1];

        // ---- S = Q K^T via ldmatrix fragments ----
        float s[8][4];
#pragma unroll
        for (int nt = 0; nt < 8; nt++) {
#pragma unroll
            for (int j = 0; j < 4; j++) s[nt][j] = 0.f;
            unsigned kf0, kf1, kf2, kf3;
            ldsm4(kf0, kf1, kf2, kf3,
                  sK + cur * KBYTES + ((nt * 8 + lrow) * KSTRIDE + lk8 * 8) * 2);
            mma_bf16(s[nt], qa[0][0], qa[0][1], qa[0][2], qa[0][3], kf0, kf1);
            mma_bf16(s[nt], qa[1][0], qa[1][1], qa[1][2], qa[1][3], kf2, kf3);
        }

        // ---- mask + exp2 ----
#pragma unroll
        for (int nt = 0; nt < 8; nt++) {
            unsigned w0 = (nt < 4) ? m0lo : m0hi;
            unsigned w1 = (nt < 4) ? m1lo : m1hi;
            int sh = (nt & 3) * 8 + 2 * tg;
            float p0 = ex2(((w0 >> sh) & 1u)       ? s[nt][0] : -64.f);
            float p1 = ex2(((w0 >> (sh + 1)) & 1u) ? s[nt][1] : -64.f);
            float p2 = ex2(((w1 >> sh) & 1u)       ? s[nt][2] : -64.f);
            float p3 = ex2(((w1 >> (sh + 1)) & 1u) ? s[nt][3] : -64.f);
            l0 += p0 + p1;
            l1 += p2 + p3;
            s[nt][0] = p0; s[nt][1] = p1; s[nt][2] = p2; s[nt][3] = p3;
        }

        // ---- O += P V via ldmatrix fragments ----
        unsigned pa[4][4];
#pragma unroll
        for (int kk = 0; kk < 4; kk++) {
            pa[kk][0] = packbf(s[2 * kk][0],     s[2 * kk][1]);
            pa[kk][1] = packbf(s[2 * kk][2],     s[2 * kk][3]);
            pa[kk][2] = packbf(s[2 * kk + 1][0], s[2 * kk + 1][1]);
            pa[kk][3] = packbf(s[2 * kk + 1][2], s[2 * kk + 1][3]);
        }
#pragma unroll
        for (int nd = 0; nd < 4; nd++) {
            unsigned vf[8];
            unsigned vaddr = sV + cur * VBYTES + ((nd * 8 + lrow) * VTSTRIDE + lk8 * 8) * 2;
            ldsm4(vf[0], vf[1], vf[2], vf[3], vaddr);
            ldsm4(vf[4], vf[5], vf[6], vf[7], vaddr + 64);
#pragma unroll
            for (int kk = 0; kk < 4; kk++)
                mma_bf16(oc[nd], pa[kk][0], pa[kk][1], pa[kk][2], pa[kk][3],
                         vf[2 * kk], vf[2 * kk + 1]);
        }
        __syncthreads();
    }

    // reduce l across the 4-lane quad (same row)
    l0 += __shfl_xor_sync(0xffffffffu, l0, 1);
    l0 += __shfl_xor_sync(0xffffffffu, l0, 2);
    l1 += __shfl_xor_sync(0xffffffffu, l1, 1);
    l1 += __shfl_xor_sync(0xffffffffu, l1, 2);

    // write UNNORMALIZED numerators; reduce kernel does the single division
    float* p0 = pacc + ((size_t)split * NN + wr + g) * DD + h * HDIM;
    float* p1 = pacc + ((size_t)split * NN + wr + g + 8) * DD + h * HDIM;
#pragma unroll
    for (int nd = 0; nd < 4; nd++) {
        int col = nd * 8 + 2 * tg;
        *reinterpret_cast<float2*>(p0 + col) = make_float2(oc[nd][0], oc[nd][1]);
        *reinterpret_cast<float2*>(p1 + col) = make_float2(oc[nd][2], oc[nd][3]);
    }
    if (tg == 0) {
        pl[((size_t)split * NN + wr + g) * HH + h] = l0;
        pl[((size_t)split * NN + wr + g + 8) * HH + h] = l1;
    }
}

// ---------------- split-K reduce ------------------------------------------
__global__ void attn_reduce_kernel(const float* __restrict__ pacc,
                                   const float* __restrict__ pl,
                                   float* __restrict__ o) {
    const int r = blockIdx.x;
    const int t = threadIdx.x;
    const int h = t >> 5;
    float s = 0.f;
#pragma unroll
    for (int sp = 0; sp < KSPLIT; sp++)
        s += pacc[((size_t)sp * NN + r) * DD + t];
    float L = 0.f;
#pragma unroll
    for (int sp = 0; sp < KSPLIT; sp++)
        L += pl[((size_t)sp * NN + r) * HH + h];
    o[(size_t)r * DD + t] = s / L;
}

// ---------------- residual add + layernorm -------------------------------
__global__ void ln_kernel(const float* __restrict__ a,
                          const float* __restrict__ res,
                          const float* __restrict__ g,
                          const float* __restrict__ beta,
                          float* __restrict__ out) {
    const int row = blockIdx.x;
    const int t = threadIdx.x;
    const int lane = t & 31, warp = t >> 5;

    float x = a[(size_t)row * DD + t] + res[(size_t)row * DD + t];
    float s = x, s2 = x * x;
#pragma unroll
    for (int off = 16; off; off >>= 1) {
        s  += __shfl_xor_sync(0xffffffffu, s, off);
        s2 += __shfl_xor_sync(0xffffffffu, s2, off);
    }
    __shared__ float sh[2][8];
    if (lane == 0) { sh[0][warp] = s; sh[1][warp] = s2; }
    __syncthreads();
    float S = 0.f, S2 = 0.f;
#pragma unroll
    for (int i = 0; i < 8; i++) { S += sh[0][i]; S2 += sh[1][i]; }

    float mu = S * (1.0f / DD);
    float var = S2 * (1.0f / DD) - mu * mu;
    float r = rsqrtf(var + EPS);
    out[(size_t)row * DD + t] = (x - mu) * r * g[t] + beta[t];
}

// ---------------- launch --------------------------------------------------
extern "C" void kernel_launch(void* const* d_in, const int* in_sizes, int n_in,
                              void* d_out, int out_size) {
    const float* x    = (const float*)d_in[0];
    const int*   adj  = (const int*)d_in[1];
    const float* Wq   = (const float*)d_in[2];
    const float* Wk   = (const float*)d_in[3];
    const float* Wv   = (const float*)d_in[4];
    const float* bq   = (const float*)d_in[5];
    const float* bk   = (const float*)d_in[6];
    const float* bv   = (const float*)d_in[7];
    const float* Wo   = (const float*)d_in[8];
    const float* bo   = (const float*)d_in[9];
    const float* g1   = (const float*)d_in[10];
    const float* be1  = (const float*)d_in[11];
    const float* W1   = (const float*)d_in[12];
    const float* b1   = (const float*)d_in[13];
    const float* W2   = (const float*)d_in[14];
    const float* b2   = (const float*)d_in[15];
    const float* g2   = (const float*)d_in[16];
    const float* be2  = (const float*)d_in[17];
    float* out = (float*)d_out;

    float *v, *o, *h, *x1, *f1, *f2, *pacc, *pl;
    __nv_bfloat16 *qb, *kb, *vt;
    unsigned *mbits;
    cudaGetSymbolAddress((void**)&v,     g_v);
    cudaGetSymbolAddress((void**)&qb,    g_qb);
    cudaGetSymbolAddress((void**)&kb,    g_kb);
    cudaGetSymbolAddress((void**)&vt,    g_vt);
    cudaGetSymbolAddress((void**)&mbits, g_mbits);
    cudaGetSymbolAddress((void**)&o,     g_o);
    cudaGetSymbolAddress((void**)&h,     g_h);
    cudaGetSymbolAddress((void**)&x1,    g_x1);
    cudaGetSymbolAddress((void**)&f1,    g_f1);
    cudaGetSymbolAddress((void**)&f2,    g_f2);
    cudaGetSymbolAddress((void**)&pacc,  g_pacc);
    cudaGetSymbolAddress((void**)&pl,    g_pl);

    const float scl = 0.17677669529663687f * 1.4426950408889634f; // 1/sqrt(32)*log2(e)

    dim3 tg(128);
    dim3 gD(DD / 64, NN / 64);
    dim3 gF1(2 * DD / 64, NN / 64);

    // mask pack (independent of projections)
    maskpack_kernel<<<NN, NN / 32>>>(adj, mbits);

    // fused QKV projection (q,k -> bf16; k pre-scaled; v -> fp32)
    qkv_tf32_kernel<<<dim3(12, NN / 64), tg>>>(x, Wq, Wk, Wv, bq, bk, bv, qb, kb, v, scl);
    vtrans_kernel<<<dim3(NN / 64, DD / 32), 256>>>(v, vt);

    // tensor-core masked attention (split-K) + reduce
    attn_mma_kernel<<<dim3(NN / 64, HH, KSPLIT), 128>>>(qb, kb, vt, mbits, pacc, pl);
    attn_reduce_kernel<<<NN, DD>>>(pacc, pl, o);

    // output projection + LN1
    gemm_tf32_kernel<<<gD, tg>>>(o, Wo, bo, h, NN, DD, DD, 0, 1.0f);
    ln_kernel<<<NN, DD>>>(h, x, g1, be1, x1);

    // FFN
    gemm_tf32_kernel<<<gF1, tg>>>(x1, W1, b1, f1, NN, 2 * DD, DD, 1, 1.0f);
    gemm_tf32_kernel<<<gD, tg>>>(f1, W2, b2, f2, NN, DD, 2 * DD, 0, 1.0f);

    // LN2 -> final output
    ln_kernel<<<NN, DD>>>(f2, x1, g2, be2, out);
}